// round 1
// baseline (speedup 1.0000x reference)
#include <cuda_runtime.h>

// ---------------- scratch (no allocation allowed) ----------------
__device__ float g_qkv[8192 * 3072];   // [B*S, 3*EMB]
__device__ float g_att[8192 * 1024];   // [B*S, EMB] (heads re-interleaved)

// ---------------- generic fp32 GEMM: C[M,N] = A[M,K] @ B[K,N] (+bias) ------
// 128x128 block tile, BK=8, 256 threads, 8x8 per-thread micro tile.
__global__ __launch_bounds__(256) void gemm128(
    const float* __restrict__ A, const float* __restrict__ B,
    const float* __restrict__ bias, float* __restrict__ C,
    int M, int N, int K)
{
    __shared__ float As[8][128];   // transposed A tile: As[k][m]
    __shared__ float Bs[8][128];   // Bs[k][n]

    const int tid  = threadIdx.x;
    const int rowg = tid >> 4;     // 0..15
    const int colg = tid & 15;     // 0..15
    const int brow = blockIdx.y * 128;
    const int bcol = blockIdx.x * 128;

    // A tile load mapping: 128 rows x 8 k, one float4 per thread
    const int a_row = tid >> 1;
    const int a_k4  = (tid & 1) * 4;
    // B tile load mapping: 8 k-rows x 128 cols, one float4 per thread
    const int b_k   = tid >> 5;
    const int b_c4  = (tid & 31) * 4;

    const float* Ap = A + (size_t)(brow + a_row) * K + a_k4;
    const float* Bp = B + (size_t)b_k * N + bcol + b_c4;

    float acc[8][8];
    #pragma unroll
    for (int i = 0; i < 8; i++)
        #pragma unroll
        for (int j = 0; j < 8; j++) acc[i][j] = 0.0f;

    for (int k0 = 0; k0 < K; k0 += 8) {
        float4 av = *(const float4*)(Ap + k0);
        float4 bv = *(const float4*)(Bp + (size_t)k0 * N);
        As[a_k4 + 0][a_row] = av.x;
        As[a_k4 + 1][a_row] = av.y;
        As[a_k4 + 2][a_row] = av.z;
        As[a_k4 + 3][a_row] = av.w;
        *(float4*)&Bs[b_k][b_c4] = bv;
        __syncthreads();

        #pragma unroll
        for (int kk = 0; kk < 8; kk++) {
            float a[8], b[8];
            *(float4*)&a[0] = *(const float4*)&As[kk][rowg * 8];
            *(float4*)&a[4] = *(const float4*)&As[kk][rowg * 8 + 4];
            *(float4*)&b[0] = *(const float4*)&Bs[kk][colg * 8];
            *(float4*)&b[4] = *(const float4*)&Bs[kk][colg * 8 + 4];
            #pragma unroll
            for (int i = 0; i < 8; i++)
                #pragma unroll
                for (int j = 0; j < 8; j++)
                    acc[i][j] = fmaf(a[i], b[j], acc[i][j]);
        }
        __syncthreads();
    }

    float bvals[8];
    #pragma unroll
    for (int j = 0; j < 8; j++)
        bvals[j] = bias ? bias[bcol + colg * 8 + j] : 0.0f;

    #pragma unroll
    for (int i = 0; i < 8; i++) {
        const int row = brow + rowg * 8 + i;
        float4 r0, r1;
        r0.x = acc[i][0] + bvals[0]; r0.y = acc[i][1] + bvals[1];
        r0.z = acc[i][2] + bvals[2]; r0.w = acc[i][3] + bvals[3];
        r1.x = acc[i][4] + bvals[4]; r1.y = acc[i][5] + bvals[5];
        r1.z = acc[i][6] + bvals[6]; r1.w = acc[i][7] + bvals[7];
        *(float4*)&C[(size_t)row * N + bcol + colg * 8]     = r0;
        *(float4*)&C[(size_t)row * N + bcol + colg * 8 + 4] = r1;
    }
}

// ---------------- causal flash attention, hd=64, BQ=BK=64 -----------------
// qkv layout: [B*S, 3072], q at col h*64, k at 1024+h*64, v at 2048+h*64.
// out layout: [B*S, 1024] with out[.., h*64+d] (heads re-interleaved).
__global__ __launch_bounds__(256) void attn64(
    const float* __restrict__ qkv, float* __restrict__ out)
{
    __shared__ float Qs[64 * 64];   // transposed: Qs[d*64 + row], pre-scaled
    __shared__ float KPs[64 * 64];  // K transposed [d*64+col]; reused as P [row*64+col]
    __shared__ float Vs[64 * 64];   // row-major: Vs[k*64 + d]

    const int qt = blockIdx.x;      // 0..31
    const int h  = blockIdx.y;      // 0..15
    const int b  = blockIdx.z;      // 0..3
    const int tid = threadIdx.x;
    const int ty = tid >> 4;        // 0..15 -> owns rows ty*4..+3
    const int tx = tid & 15;        // 0..15 -> owns cols tx*4..+3
    const int S = 2048, D3 = 3072;

    // load Q tile (transposed, scaled by 1/sqrt(64))
    const float* qb = qkv + ((size_t)(b * S) + qt * 64) * D3 + h * 64;
    for (int i = tid; i < 64 * 16; i += 256) {
        int r  = i >> 4;
        int c4 = (i & 15) * 4;
        float4 v = *(const float4*)(qb + (size_t)r * D3 + c4);
        Qs[(c4 + 0) * 64 + r] = v.x * 0.125f;
        Qs[(c4 + 1) * 64 + r] = v.y * 0.125f;
        Qs[(c4 + 2) * 64 + r] = v.z * 0.125f;
        Qs[(c4 + 3) * 64 + r] = v.w * 0.125f;
    }

    float o[4][4];
    float m_i[4], l_i[4];
    #pragma unroll
    for (int i = 0; i < 4; i++) {
        m_i[i] = -1e30f; l_i[i] = 0.0f;
        #pragma unroll
        for (int j = 0; j < 4; j++) o[i][j] = 0.0f;
    }

    for (int kt = 0; kt <= qt; kt++) {
        __syncthreads();  // previous-iter P/V reads complete before overwrite
        const float* kb = qkv + ((size_t)(b * S) + kt * 64) * D3 + 1024 + h * 64;
        for (int i = tid; i < 64 * 16; i += 256) {
            int r  = i >> 4;
            int c4 = (i & 15) * 4;
            float4 kv = *(const float4*)(kb + (size_t)r * D3 + c4);
            KPs[(c4 + 0) * 64 + r] = kv.x;
            KPs[(c4 + 1) * 64 + r] = kv.y;
            KPs[(c4 + 2) * 64 + r] = kv.z;
            KPs[(c4 + 3) * 64 + r] = kv.w;
            float4 vv = *(const float4*)(kb + 1024 + (size_t)r * D3 + c4);
            *(float4*)&Vs[r * 64 + c4] = vv;
        }
        __syncthreads();

        // scores S = (Q/8) @ K^T   (64x64, 4x4 per thread)
        float s[4][4];
        #pragma unroll
        for (int i = 0; i < 4; i++)
            #pragma unroll
            for (int j = 0; j < 4; j++) s[i][j] = 0.0f;

        #pragma unroll 8
        for (int d = 0; d < 64; d++) {
            const float4 qa = *(const float4*)&Qs[d * 64 + ty * 4];
            const float4 ka = *(const float4*)&KPs[d * 64 + tx * 4];
            const float qv[4] = {qa.x, qa.y, qa.z, qa.w};
            const float kv[4] = {ka.x, ka.y, ka.z, ka.w};
            #pragma unroll
            for (int i = 0; i < 4; i++)
                #pragma unroll
                for (int j = 0; j < 4; j++)
                    s[i][j] = fmaf(qv[i], kv[j], s[i][j]);
        }

        // causal mask only on diagonal tile
        if (kt == qt) {
            #pragma unroll
            for (int i = 0; i < 4; i++)
                #pragma unroll
                for (int j = 0; j < 4; j++)
                    if (tx * 4 + j > ty * 4 + i) s[i][j] = -1e30f;
        }

        // online softmax update (row stats reduced across the 16 tx lanes)
        #pragma unroll
        for (int i = 0; i < 4; i++) {
            float mx = fmaxf(fmaxf(s[i][0], s[i][1]), fmaxf(s[i][2], s[i][3]));
            mx = fmaxf(mx, __shfl_xor_sync(0xffffffffu, mx, 1, 16));
            mx = fmaxf(mx, __shfl_xor_sync(0xffffffffu, mx, 2, 16));
            mx = fmaxf(mx, __shfl_xor_sync(0xffffffffu, mx, 4, 16));
            mx = fmaxf(mx, __shfl_xor_sync(0xffffffffu, mx, 8, 16));
            const float mnew  = fmaxf(m_i[i], mx);
            const float alpha = __expf(m_i[i] - mnew);
            m_i[i] = mnew;
            float rs = 0.0f;
            #pragma unroll
            for (int j = 0; j < 4; j++) {
                s[i][j] = __expf(s[i][j] - mnew);
                rs += s[i][j];
            }
            rs += __shfl_xor_sync(0xffffffffu, rs, 1, 16);
            rs += __shfl_xor_sync(0xffffffffu, rs, 2, 16);
            rs += __shfl_xor_sync(0xffffffffu, rs, 4, 16);
            rs += __shfl_xor_sync(0xffffffffu, rs, 8, 16);
            l_i[i] = l_i[i] * alpha + rs;
            #pragma unroll
            for (int j = 0; j < 4; j++) o[i][j] *= alpha;
        }

        __syncthreads();  // all K reads from KPs done
        #pragma unroll
        for (int i = 0; i < 4; i++)
            #pragma unroll
            for (int j = 0; j < 4; j++)
                KPs[(ty * 4 + i) * 64 + tx * 4 + j] = s[i][j];
        __syncthreads();

        // O += P @ V
        #pragma unroll 8
        for (int kk = 0; kk < 64; kk++) {
            float p[4];
            p[0] = KPs[(ty * 4 + 0) * 64 + kk];
            p[1] = KPs[(ty * 4 + 1) * 64 + kk];
            p[2] = KPs[(ty * 4 + 2) * 64 + kk];
            p[3] = KPs[(ty * 4 + 3) * 64 + kk];
            const float4 va = *(const float4*)&Vs[kk * 64 + tx * 4];
            const float vv[4] = {va.x, va.y, va.z, va.w};
            #pragma unroll
            for (int i = 0; i < 4; i++)
                #pragma unroll
                for (int j = 0; j < 4; j++)
                    o[i][j] = fmaf(p[i], vv[j], o[i][j]);
        }
    }

    // epilogue: normalize and store (heads interleaved back to [B,S,D])
    float* ob = out + ((size_t)(b * S) + qt * 64) * 1024 + h * 64;
    #pragma unroll
    for (int i = 0; i < 4; i++) {
        const float inv = 1.0f / l_i[i];
        float4 r;
        r.x = o[i][0] * inv; r.y = o[i][1] * inv;
        r.z = o[i][2] * inv; r.w = o[i][3] * inv;
        *(float4*)&ob[(size_t)(ty * 4 + i) * 1024 + tx * 4] = r;
    }
}

// ---------------- launch -------------------------------------------------
extern "C" void kernel_launch(void* const* d_in, const int* in_sizes, int n_in,
                              void* d_out, int out_size)
{
    const float* x      = (const float*)d_in[0];   // [4,2048,1024]
    const float* W_qkv  = (const float*)d_in[1];   // [1024,3072]
    const float* W_proj = (const float*)d_in[2];   // [1024,1024]
    const float* b_proj = (const float*)d_in[3];   // [1024]
    float* out = (float*)d_out;                    // [4,2048,1024]

    float* qkv = nullptr;
    float* att = nullptr;
    cudaGetSymbolAddress((void**)&qkv, g_qkv);
    cudaGetSymbolAddress((void**)&att, g_att);

    const int M = 8192;  // B*S

    // 1) qkv = x @ W_qkv
    gemm128<<<dim3(3072 / 128, M / 128), 256>>>(x, W_qkv, nullptr, qkv,
                                                M, 3072, 1024);
    // 2) causal flash attention per (q-tile, head, batch)
    attn64<<<dim3(32, 16, 4), 256>>>(qkv, att);
    // 3) out = att @ W_proj + b_proj
    gemm128<<<dim3(1024 / 128, M / 128), 256>>>(att, W_proj, b_proj, out,
                                                M, 1024, 1024);
}

// round 3
// speedup vs baseline: 1.1888x; 1.1888x over previous
#include <cuda_runtime.h>
#include <cstdint>

// ---------------- scratch (no allocation allowed) ----------------
__device__ float g_qkv[8192 * 3072];   // [B*S, 3*EMB]
__device__ float g_att[8192 * 1024];   // [B*S, EMB]
__device__ float g_wqT[3072 * 1024];   // W_qkv transposed [N,K], tf32-rounded
__device__ float g_wpT[1024 * 1024];   // W_proj transposed [N,K], tf32-rounded

// ---------------- helpers --------------------------------------
__device__ __forceinline__ uint32_t f2tf32(float v) {
    uint32_t u;
    asm("cvt.rna.tf32.f32 %0, %1;" : "=r"(u) : "f"(v));
    return u;
}

__device__ __forceinline__ void mma_tf32(float c[4], const uint4& a, const uint2& b) {
    asm volatile(
        "mma.sync.aligned.m16n8k8.row.col.f32.tf32.tf32.f32 "
        "{%0,%1,%2,%3}, {%4,%5,%6,%7}, {%8,%9}, {%0,%1,%2,%3};"
        : "+f"(c[0]), "+f"(c[1]), "+f"(c[2]), "+f"(c[3])
        : "r"(a.x), "r"(a.y), "r"(a.z), "r"(a.w), "r"(b.x), "r"(b.y));
}

// ---------------- weight transpose + tf32 rounding ------------------------
__global__ __launch_bounds__(256) void transpose_rna(
    const float* __restrict__ in, float* __restrict__ out, int R, int C)
{
    __shared__ float t[32][33];
    const int c0 = blockIdx.x * 32, r0 = blockIdx.y * 32;
    const int x = threadIdx.x & 31, y = threadIdx.x >> 5;  // 32x8
    #pragma unroll
    for (int i = 0; i < 32; i += 8) {
        float v = in[(size_t)(r0 + y + i) * C + c0 + x];
        t[y + i][x] = __uint_as_float(f2tf32(v));
    }
    __syncthreads();
    #pragma unroll
    for (int i = 0; i < 32; i += 8)
        out[(size_t)(c0 + y + i) * R + r0 + x] = t[x][y + i];
}

// ---------------- tf32 mma.sync GEMM: C[M,N] = A[M,K] @ BT[N,K]^T (+bias) -
// 128x128 CTA tile, BK=16, 256 threads = 4x2 warp grid, warp tile 32x64.
// Smem holds fragment-permuted tiles so the hot loop is lds.128/lds.64
// conflict-free.
__global__ __launch_bounds__(256, 2) void gemm_mma(
    const float* __restrict__ A, const float* __restrict__ BT,
    const float* __restrict__ bias, float* __restrict__ C,
    int M, int N, int K)
{
    // As: [kstep(2)][mtile(8)][lane(32)][reg(4)]  (8KB)
    // Bs: [kstep(2)][ntile(16)][lane(32)][reg(2)] (8KB)
    __shared__ float As[2048];
    __shared__ float Bs[2048];

    const int tid  = threadIdx.x;
    const int wid  = tid >> 5, lane = tid & 31;
    const int wr   = wid & 3;       // warp row: m-tiles wr*2, wr*2+1
    const int wc   = wid >> 2;      // warp col: n-tiles wc*8 .. +7
    const int brow = blockIdx.y * 128, bcol = blockIdx.x * 128;

    // staging mapping: thread owns row r, k-cols c0..c0+7 (one kstep)
    const int r     = tid >> 1;          // 0..127
    const int c0    = (tid & 1) * 8;     // 0 or 8
    const int ks    = c0 >> 3;           // kstep of this thread's 8 elems
    const int mt_st = r >> 4;
    const int rbit  = (r >> 3) & 1;
    const int nt_st = r >> 3;
    const int gB    = r & 7;

    const float* Ap = A  + (size_t)(brow + r) * K + c0;
    const float* Bp = BT + (size_t)(bcol + r) * K + c0;

    float acc[2][8][4];
    #pragma unroll
    for (int i = 0; i < 2; i++)
        #pragma unroll
        for (int j = 0; j < 8; j++)
            #pragma unroll
            for (int e = 0; e < 4; e++) acc[i][j][e] = 0.0f;

    for (int kt = 0; kt < K; kt += 16) {
        float4 av0 = *(const float4*)(Ap + kt);
        float4 av1 = *(const float4*)(Ap + kt + 4);
        float4 bv0 = *(const float4*)(Bp + kt);
        float4 bv1 = *(const float4*)(Bp + kt + 4);
        const float ae[8] = {av0.x, av0.y, av0.z, av0.w, av1.x, av1.y, av1.z, av1.w};
        const float be[8] = {bv0.x, bv0.y, bv0.z, bv0.w, bv1.x, bv1.y, bv1.z, bv1.w};
        #pragma unroll
        for (int e = 0; e < 8; e++) {
            // A frag: element (r%16, e) of m-tile -> lane ((r&7)<<2)|(e&3),
            // reg ((e>>2)<<1)|rbit
            const int laneA = ((r & 7) << 2) | (e & 3);
            const int regA  = ((e >> 2) << 1) | rbit;
            As[((ks * 8 + mt_st) * 32 + laneA) * 4 + regA] =
                __uint_as_float(f2tf32(ae[e]));
            // B frag: element (n=r%8, k=e) of n-tile -> lane (gB<<2)|(e&3), reg e>>2
            const int laneB = (gB << 2) | (e & 3);
            const int regB  = e >> 2;
            Bs[((ks * 16 + nt_st) * 32 + laneB) * 2 + regB] =
                __uint_as_float(f2tf32(be[e]));
        }
        __syncthreads();

        #pragma unroll
        for (int s = 0; s < 2; s++) {
            uint4 af[2];
            af[0] = ((const uint4*)As)[(s * 8 + wr * 2 + 0) * 32 + lane];
            af[1] = ((const uint4*)As)[(s * 8 + wr * 2 + 1) * 32 + lane];
            uint2 bf[8];
            #pragma unroll
            for (int j = 0; j < 8; j++)
                bf[j] = ((const uint2*)Bs)[(s * 16 + wc * 8 + j) * 32 + lane];
            #pragma unroll
            for (int i = 0; i < 2; i++)
                #pragma unroll
                for (int j = 0; j < 8; j++)
                    mma_tf32(acc[i][j], af[i], bf[j]);
        }
        __syncthreads();
    }

    // epilogue: c0,c1 -> (row g, col 2q..2q+1); c2,c3 -> (row g+8, same cols)
    const int g = lane >> 2, q = lane & 3;
    #pragma unroll
    for (int i = 0; i < 2; i++) {
        const int row0 = brow + (wr * 2 + i) * 16 + g;
        #pragma unroll
        for (int j = 0; j < 8; j++) {
            const int col = bcol + wc * 64 + j * 8 + q * 2;
            float b0 = 0.0f, b1 = 0.0f;
            if (bias) { b0 = bias[col]; b1 = bias[col + 1]; }
            float2 v0, v1;
            v0.x = acc[i][j][0] + b0; v0.y = acc[i][j][1] + b1;
            v1.x = acc[i][j][2] + b0; v1.y = acc[i][j][3] + b1;
            *(float2*)&C[(size_t)row0 * N + col]       = v0;
            *(float2*)&C[(size_t)(row0 + 8) * N + col] = v1;
        }
    }
}

// ---------------- causal flash attention, hd=64, BQ=BK=64 -----------------
__global__ __launch_bounds__(256) void attn64(
    const float* __restrict__ qkv, float* __restrict__ out)
{
    __shared__ float Qs[64 * 64];
    __shared__ float KPs[64 * 64];
    __shared__ float Vs[64 * 64];

    const int qt = blockIdx.x;
    const int h  = blockIdx.y;
    const int b  = blockIdx.z;
    const int tid = threadIdx.x;
    const int ty = tid >> 4;
    const int tx = tid & 15;
    const int S = 2048, D3 = 3072;

    const float* qb = qkv + ((size_t)(b * S) + qt * 64) * D3 + h * 64;
    for (int i = tid; i < 64 * 16; i += 256) {
        int r  = i >> 4;
        int c4 = (i & 15) * 4;
        float4 v = *(const float4*)(qb + (size_t)r * D3 + c4);
        Qs[(c4 + 0) * 64 + r] = v.x * 0.125f;
        Qs[(c4 + 1) * 64 + r] = v.y * 0.125f;
        Qs[(c4 + 2) * 64 + r] = v.z * 0.125f;
        Qs[(c4 + 3) * 64 + r] = v.w * 0.125f;
    }

    float o[4][4];
    float m_i[4], l_i[4];
    #pragma unroll
    for (int i = 0; i < 4; i++) {
        m_i[i] = -1e30f; l_i[i] = 0.0f;
        #pragma unroll
        for (int j = 0; j < 4; j++) o[i][j] = 0.0f;
    }

    for (int kt = 0; kt <= qt; kt++) {
        __syncthreads();
        const float* kb = qkv + ((size_t)(b * S) + kt * 64) * D3 + 1024 + h * 64;
        for (int i = tid; i < 64 * 16; i += 256) {
            int r  = i >> 4;
            int c4 = (i & 15) * 4;
            float4 kv = *(const float4*)(kb + (size_t)r * D3 + c4);
            KPs[(c4 + 0) * 64 + r] = kv.x;
            KPs[(c4 + 1) * 64 + r] = kv.y;
            KPs[(c4 + 2) * 64 + r] = kv.z;
            KPs[(c4 + 3) * 64 + r] = kv.w;
            float4 vv = *(const float4*)(kb + 1024 + (size_t)r * D3 + c4);
            *(float4*)&Vs[r * 64 + c4] = vv;
        }
        __syncthreads();

        float s[4][4];
        #pragma unroll
        for (int i = 0; i < 4; i++)
            #pragma unroll
            for (int j = 0; j < 4; j++) s[i][j] = 0.0f;

        #pragma unroll 8
        for (int d = 0; d < 64; d++) {
            const float4 qa = *(const float4*)&Qs[d * 64 + ty * 4];
            const float4 ka = *(const float4*)&KPs[d * 64 + tx * 4];
            const float qv[4] = {qa.x, qa.y, qa.z, qa.w};
            const float kv[4] = {ka.x, ka.y, ka.z, ka.w};
            #pragma unroll
            for (int i = 0; i < 4; i++)
                #pragma unroll
                for (int j = 0; j < 4; j++)
                    s[i][j] = fmaf(qv[i], kv[j], s[i][j]);
        }

        if (kt == qt) {
            #pragma unroll
            for (int i = 0; i < 4; i++)
                #pragma unroll
                for (int j = 0; j < 4; j++)
                    if (tx * 4 + j > ty * 4 + i) s[i][j] = -1e30f;
        }

        #pragma unroll
        for (int i = 0; i < 4; i++) {
            float mx = fmaxf(fmaxf(s[i][0], s[i][1]), fmaxf(s[i][2], s[i][3]));
            mx = fmaxf(mx, __shfl_xor_sync(0xffffffffu, mx, 1, 16));
            mx = fmaxf(mx, __shfl_xor_sync(0xffffffffu, mx, 2, 16));
            mx = fmaxf(mx, __shfl_xor_sync(0xffffffffu, mx, 4, 16));
            mx = fmaxf(mx, __shfl_xor_sync(0xffffffffu, mx, 8, 16));
            const float mnew  = fmaxf(m_i[i], mx);
            const float alpha = __expf(m_i[i] - mnew);
            m_i[i] = mnew;
            float rs = 0.0f;
            #pragma unroll
            for (int j = 0; j < 4; j++) {
                s[i][j] = __expf(s[i][j] - mnew);
                rs += s[i][j];
            }
            rs += __shfl_xor_sync(0xffffffffu, rs, 1, 16);
            rs += __shfl_xor_sync(0xffffffffu, rs, 2, 16);
            rs += __shfl_xor_sync(0xffffffffu, rs, 4, 16);
            rs += __shfl_xor_sync(0xffffffffu, rs, 8, 16);
            l_i[i] = l_i[i] * alpha + rs;
            #pragma unroll
            for (int j = 0; j < 4; j++) o[i][j] *= alpha;
        }

        __syncthreads();
        #pragma unroll
        for (int i = 0; i < 4; i++)
            #pragma unroll
            for (int j = 0; j < 4; j++)
                KPs[(ty * 4 + i) * 64 + tx * 4 + j] = s[i][j];
        __syncthreads();

        #pragma unroll 8
        for (int kk = 0; kk < 64; kk++) {
            float p[4];
            p[0] = KPs[(ty * 4 + 0) * 64 + kk];
            p[1] = KPs[(ty * 4 + 1) * 64 + kk];
            p[2] = KPs[(ty * 4 + 2) * 64 + kk];
            p[3] = KPs[(ty * 4 + 3) * 64 + kk];
            const float4 va = *(const float4*)&Vs[kk * 64 + tx * 4];
            const float vv[4] = {va.x, va.y, va.z, va.w};
            #pragma unroll
            for (int i = 0; i < 4; i++)
                #pragma unroll
                for (int j = 0; j < 4; j++)
                    o[i][j] = fmaf(p[i], vv[j], o[i][j]);
        }
    }

    float* ob = out + ((size_t)(b * S) + qt * 64) * 1024 + h * 64;
    #pragma unroll
    for (int i = 0; i < 4; i++) {
        const float inv = 1.0f / l_i[i];
        float4 rr;
        rr.x = o[i][0] * inv; rr.y = o[i][1] * inv;
        rr.z = o[i][2] * inv; rr.w = o[i][3] * inv;
        *(float4*)&ob[(size_t)(ty * 4 + i) * 1024 + tx * 4] = rr;
    }
}

// ---------------- launch -------------------------------------------------
extern "C" void kernel_launch(void* const* d_in, const int* in_sizes, int n_in,
                              void* d_out, int out_size)
{
    const float* x      = (const float*)d_in[0];   // [4,2048,1024]
    const float* W_qkv  = (const float*)d_in[1];   // [1024,3072]
    const float* W_proj = (const float*)d_in[2];   // [1024,1024]
    const float* b_proj = (const float*)d_in[3];   // [1024]
    float* out = (float*)d_out;

    float *qkv = nullptr, *att = nullptr, *wqT = nullptr, *wpT = nullptr;
    cudaGetSymbolAddress((void**)&qkv, g_qkv);
    cudaGetSymbolAddress((void**)&att, g_att);
    cudaGetSymbolAddress((void**)&wqT, g_wqT);
    cudaGetSymbolAddress((void**)&wpT, g_wpT);

    const int M = 8192;

    // 0) transpose + tf32-round weights
    transpose_rna<<<dim3(3072 / 32, 1024 / 32), 256>>>(W_qkv, wqT, 1024, 3072);
    transpose_rna<<<dim3(1024 / 32, 1024 / 32), 256>>>(W_proj, wpT, 1024, 1024);

    // 1) qkv = x @ W_qkv  (tf32 mma.sync)
    gemm_mma<<<dim3(3072 / 128, M / 128), 256>>>(x, wqT, nullptr, qkv,
                                                 M, 3072, 1024);
    // 2) causal flash attention
    attn64<<<dim3(32, 16, 4), 256>>>(qkv, att);

    // 3) out = att @ W_proj + b_proj
    gemm_mma<<<dim3(1024 / 128, M / 128), 256>>>(att, wpT, b_proj, out,
                                                 M, 1024, 1024);
}

// round 6
// speedup vs baseline: 1.7135x; 1.4414x over previous
#include <cuda_runtime.h>
#include <cstdint>

// ---------------- scratch (no allocation allowed) ----------------
__device__ float g_qkv[8192 * 3072];   // [B*S, 3*EMB]
__device__ float g_att[8192 * 1024];   // [B*S, EMB]
__device__ float g_wqT[3072 * 1024];   // W_qkv transposed [N,K], tf32-rounded
__device__ float g_wpT[1024 * 1024];   // W_proj transposed [N,K], tf32-rounded

// ---------------- helpers --------------------------------------
__device__ __forceinline__ uint32_t f2tf32(float v) {
    uint32_t u;
    asm("cvt.rna.tf32.f32 %0, %1;" : "=r"(u) : "f"(v));
    return u;
}
__device__ __forceinline__ float tf32f(float v) {
    return __uint_as_float(f2tf32(v));
}

__device__ __forceinline__ void mma_tf32(float c[4], const uint4& a, const uint2& b) {
    asm volatile(
        "mma.sync.aligned.m16n8k8.row.col.f32.tf32.tf32.f32 "
        "{%0,%1,%2,%3}, {%4,%5,%6,%7}, {%8,%9}, {%0,%1,%2,%3};"
        : "+f"(c[0]), "+f"(c[1]), "+f"(c[2]), "+f"(c[3])
        : "r"(a.x), "r"(a.y), "r"(a.z), "r"(a.w), "r"(b.x), "r"(b.y));
}

// ---------------- weight transpose + tf32 rounding ------------------------
__global__ __launch_bounds__(256) void transpose_rna(
    const float* __restrict__ in, float* __restrict__ out, int R, int C)
{
    __shared__ float t[32][33];
    const int c0 = blockIdx.x * 32, r0 = blockIdx.y * 32;
    const int x = threadIdx.x & 31, y = threadIdx.x >> 5;  // 32x8
    #pragma unroll
    for (int i = 0; i < 32; i += 8) {
        float v = in[(size_t)(r0 + y + i) * C + c0 + x];
        t[y + i][x] = tf32f(v);
    }
    __syncthreads();
    #pragma unroll
    for (int i = 0; i < 32; i += 8)
        out[(size_t)(c0 + y + i) * R + r0 + x] = t[x][y + i];
}

// ---------------- tf32 mma.sync GEMM (unchanged, verified) ----------------
__global__ __launch_bounds__(256, 2) void gemm_mma(
    const float* __restrict__ A, const float* __restrict__ BT,
    const float* __restrict__ bias, float* __restrict__ C,
    int M, int N, int K)
{
    __shared__ float As[2048];
    __shared__ float Bs[2048];

    const int tid  = threadIdx.x;
    const int wid  = tid >> 5, lane = tid & 31;
    const int wr   = wid & 3;
    const int wc   = wid >> 2;
    const int brow = blockIdx.y * 128, bcol = blockIdx.x * 128;

    const int r     = tid >> 1;
    const int c0    = (tid & 1) * 8;
    const int ks    = c0 >> 3;
    const int mt_st = r >> 4;
    const int rbit  = (r >> 3) & 1;
    const int nt_st = r >> 3;
    const int gB    = r & 7;

    const float* Ap = A  + (size_t)(brow + r) * K + c0;
    const float* Bp = BT + (size_t)(bcol + r) * K + c0;

    float acc[2][8][4];
    #pragma unroll
    for (int i = 0; i < 2; i++)
        #pragma unroll
        for (int j = 0; j < 8; j++)
            #pragma unroll
            for (int e = 0; e < 4; e++) acc[i][j][e] = 0.0f;

    for (int kt = 0; kt < K; kt += 16) {
        float4 av0 = *(const float4*)(Ap + kt);
        float4 av1 = *(const float4*)(Ap + kt + 4);
        float4 bv0 = *(const float4*)(Bp + kt);
        float4 bv1 = *(const float4*)(Bp + kt + 4);
        const float ae[8] = {av0.x, av0.y, av0.z, av0.w, av1.x, av1.y, av1.z, av1.w};
        const float be[8] = {bv0.x, bv0.y, bv0.z, bv0.w, bv1.x, bv1.y, bv1.z, bv1.w};
        #pragma unroll
        for (int e = 0; e < 8; e++) {
            const int laneA = ((r & 7) << 2) | (e & 3);
            const int regA  = ((e >> 2) << 1) | rbit;
            As[((ks * 8 + mt_st) * 32 + laneA) * 4 + regA] = tf32f(ae[e]);
            const int laneB = (gB << 2) | (e & 3);
            const int regB  = e >> 2;
            Bs[((ks * 16 + nt_st) * 32 + laneB) * 2 + regB] = tf32f(be[e]);
        }
        __syncthreads();

        #pragma unroll
        for (int s = 0; s < 2; s++) {
            uint4 af[2];
            af[0] = ((const uint4*)As)[(s * 8 + wr * 2 + 0) * 32 + lane];
            af[1] = ((const uint4*)As)[(s * 8 + wr * 2 + 1) * 32 + lane];
            uint2 bf[8];
            #pragma unroll
            for (int j = 0; j < 8; j++)
                bf[j] = ((const uint2*)Bs)[(s * 16 + wc * 8 + j) * 32 + lane];
            #pragma unroll
            for (int i = 0; i < 2; i++)
                #pragma unroll
                for (int j = 0; j < 8; j++)
                    mma_tf32(acc[i][j], af[i], bf[j]);
        }
        __syncthreads();
    }

    const int g = lane >> 2, q = lane & 3;
    #pragma unroll
    for (int i = 0; i < 2; i++) {
        const int row0 = brow + (wr * 2 + i) * 16 + g;
        #pragma unroll
        for (int j = 0; j < 8; j++) {
            const int col = bcol + wc * 64 + j * 8 + q * 2;
            float b0 = 0.0f, b1 = 0.0f;
            if (bias) { b0 = bias[col]; b1 = bias[col + 1]; }
            float2 v0, v1;
            v0.x = acc[i][j][0] + b0; v0.y = acc[i][j][1] + b1;
            v1.x = acc[i][j][2] + b0; v1.y = acc[i][j][3] + b1;
            *(float2*)&C[(size_t)row0 * N + col]       = v0;
            *(float2*)&C[(size_t)(row0 + 8) * N + col] = v1;
        }
    }
}

// ---------------- tf32 mma flash attention, BQ=128, BK=64 -----------------
// 256 threads = 8 warps; warp w owns q rows [w*16, w*16+16).
// All fragments fetched by explicit per-lane LDS at documented (row,col).
// Smem (pitch 68 floats = 272B, 16B-aligned rows; 4g+q bank pattern ->
// conflict-free fragment loads):
//   Qs[128][68]  Q/8 tf32 ; Ks[64][68] K tf32 ; Vt[64][68] V^T tf32 (d, kv)
//   Ps[128][68]  P tf32 (per-warp-private 16-row slices)
static constexpr int AP = 68;
static constexpr int ATTN_SMEM = (128 * AP + 64 * AP + 64 * AP + 128 * AP) * 4;

__global__ __launch_bounds__(256) void attn_tc(
    const float* __restrict__ qkv, float* __restrict__ out)
{
    extern __shared__ float sm[];
    float* Qs = sm;                       // 128*AP
    float* Ks = Qs + 128 * AP;            // 64*AP
    float* Vt = Ks + 64 * AP;             // 64*AP
    float* Ps = Vt + 64 * AP;             // 128*AP

    const int qt = (int)gridDim.x - 1 - (int)blockIdx.x;  // heavy tiles first
    const int h  = blockIdx.y;
    const int b  = blockIdx.z;
    const int tid = threadIdx.x, w = tid >> 5, lane = tid & 31;
    const int g = lane >> 2, q = lane & 3;
    const int S = 2048, D3 = 3072;

    // ---- stage Q once (row-major, scaled by 1/8, tf32-rounded) ----
    const float* Qb = qkv + ((size_t)(b * S) + qt * 128) * D3 + h * 64;
    for (int i = tid; i < 128 * 16; i += 256) {
        const int r = i >> 4, c4 = (i & 15) << 2;
        float4 v = *(const float4*)(Qb + (size_t)r * D3 + c4);
        float4 o4;
        o4.x = tf32f(v.x * 0.125f); o4.y = tf32f(v.y * 0.125f);
        o4.z = tf32f(v.z * 0.125f); o4.w = tf32f(v.w * 0.125f);
        *(float4*)&Qs[r * AP + c4] = o4;
    }

    float s[8][4], o[8][4];
    float m0 = -1e30f, m1 = -1e30f, l0 = 0.0f, l1 = 0.0f;
    #pragma unroll
    for (int j = 0; j < 8; j++)
        #pragma unroll
        for (int e = 0; e < 4; e++) o[j][e] = 0.0f;

    const int pr = w * 16 + g;   // this lane's P/Q row (and +8)

    const int ktmax = 2 * qt + 1;
    for (int kt = 0; kt <= ktmax; kt++) {
        __syncthreads();  // prior-iter Ks/Vt reads complete
        // ---- stage K tile (row-major kv x d) ----
        const float* Kb = qkv + ((size_t)(b * S) + kt * 64) * D3 + 1024 + h * 64;
        for (int i = tid; i < 64 * 16; i += 256) {
            const int r = i >> 4, c4 = (i & 15) << 2;
            float4 v = *(const float4*)(Kb + (size_t)r * D3 + c4);
            float4 o4;
            o4.x = tf32f(v.x); o4.y = tf32f(v.y);
            o4.z = tf32f(v.z); o4.w = tf32f(v.w);
            *(float4*)&Ks[r * AP + c4] = o4;
        }
        // ---- stage V tile transposed: Vt[d][kv] ----
        const float* Vb = qkv + ((size_t)(b * S) + kt * 64) * D3 + 2048 + h * 64;
        for (int i = tid; i < 64 * 16; i += 256) {
            const int r = i >> 4, c4 = (i & 15) << 2;
            float4 v = *(const float4*)(Vb + (size_t)r * D3 + c4);
            Vt[(c4 + 0) * AP + r] = tf32f(v.x);
            Vt[(c4 + 1) * AP + r] = tf32f(v.y);
            Vt[(c4 + 2) * AP + r] = tf32f(v.z);
            Vt[(c4 + 3) * AP + r] = tf32f(v.w);
        }
        __syncthreads();

        // ---- S = (Q/8) @ K^T : per-lane explicit fragment gathers ----
        #pragma unroll
        for (int j = 0; j < 8; j++)
            #pragma unroll
            for (int e = 0; e < 4; e++) s[j][e] = 0.0f;

        #pragma unroll
        for (int kc = 0; kc < 8; kc++) {
            uint4 a;
            a.x = __float_as_uint(Qs[pr * AP + kc * 8 + q]);          // (g,   k)
            a.y = __float_as_uint(Qs[(pr + 8) * AP + kc * 8 + q]);    // (g+8, k)
            a.z = __float_as_uint(Qs[pr * AP + kc * 8 + q + 4]);      // (g,   k+4)
            a.w = __float_as_uint(Qs[(pr + 8) * AP + kc * 8 + q + 4]);// (g+8, k+4)
            #pragma unroll
            for (int nt = 0; nt < 8; nt++) {
                uint2 bb;
                bb.x = __float_as_uint(Ks[(nt * 8 + g) * AP + kc * 8 + q]);
                bb.y = __float_as_uint(Ks[(nt * 8 + g) * AP + kc * 8 + q + 4]);
                mma_tf32(s[nt], a, bb);
            }
        }

        // ---- causal mask on diagonal tiles ----
        if (kt >= 2 * qt) {
            const int r0  = qt * 128 + pr;
            const int kvb = kt * 64 + 2 * q;
            #pragma unroll
            for (int nt = 0; nt < 8; nt++) {
                const int c = kvb + nt * 8;
                if (c     > r0)     s[nt][0] = -1e30f;
                if (c + 1 > r0)     s[nt][1] = -1e30f;
                if (c     > r0 + 8) s[nt][2] = -1e30f;
                if (c + 1 > r0 + 8) s[nt][3] = -1e30f;
            }
        }

        // ---- online softmax on C-frags (rows g / g+8) ----
        float mx0 = -1e30f, mx1 = -1e30f;
        #pragma unroll
        for (int nt = 0; nt < 8; nt++) {
            mx0 = fmaxf(mx0, fmaxf(s[nt][0], s[nt][1]));
            mx1 = fmaxf(mx1, fmaxf(s[nt][2], s[nt][3]));
        }
        mx0 = fmaxf(mx0, __shfl_xor_sync(0xffffffffu, mx0, 1, 4));
        mx0 = fmaxf(mx0, __shfl_xor_sync(0xffffffffu, mx0, 2, 4));
        mx1 = fmaxf(mx1, __shfl_xor_sync(0xffffffffu, mx1, 1, 4));
        mx1 = fmaxf(mx1, __shfl_xor_sync(0xffffffffu, mx1, 2, 4));

        const float mn0 = fmaxf(m0, mx0), mn1 = fmaxf(m1, mx1);
        const float al0 = __expf(m0 - mn0), al1 = __expf(m1 - mn1);
        m0 = mn0; m1 = mn1;

        float rs0 = 0.0f, rs1 = 0.0f;
        #pragma unroll
        for (int nt = 0; nt < 8; nt++) {
            s[nt][0] = __expf(s[nt][0] - mn0); rs0 += s[nt][0];
            s[nt][1] = __expf(s[nt][1] - mn0); rs0 += s[nt][1];
            s[nt][2] = __expf(s[nt][2] - mn1); rs1 += s[nt][2];
            s[nt][3] = __expf(s[nt][3] - mn1); rs1 += s[nt][3];
        }
        rs0 += __shfl_xor_sync(0xffffffffu, rs0, 1, 4);
        rs0 += __shfl_xor_sync(0xffffffffu, rs0, 2, 4);
        rs1 += __shfl_xor_sync(0xffffffffu, rs1, 1, 4);
        rs1 += __shfl_xor_sync(0xffffffffu, rs1, 2, 4);
        l0 = l0 * al0 + rs0;
        l1 = l1 * al1 + rs1;

        #pragma unroll
        for (int j = 0; j < 8; j++) {
            o[j][0] *= al0; o[j][1] *= al0;
            o[j][2] *= al1; o[j][3] *= al1;
        }

        // ---- P -> smem via verified C-frag mapping (warp-private rows) ----
        #pragma unroll
        for (int nt = 0; nt < 8; nt++) {
            Ps[pr * AP + nt * 8 + 2 * q]           = tf32f(s[nt][0]);
            Ps[pr * AP + nt * 8 + 2 * q + 1]       = tf32f(s[nt][1]);
            Ps[(pr + 8) * AP + nt * 8 + 2 * q]     = tf32f(s[nt][2]);
            Ps[(pr + 8) * AP + nt * 8 + 2 * q + 1] = tf32f(s[nt][3]);
        }
        __syncwarp();

        // ---- O += P @ V ----
        #pragma unroll
        for (int kc = 0; kc < 8; kc++) {
            uint4 a;
            a.x = __float_as_uint(Ps[pr * AP + kc * 8 + q]);
            a.y = __float_as_uint(Ps[(pr + 8) * AP + kc * 8 + q]);
            a.z = __float_as_uint(Ps[pr * AP + kc * 8 + q + 4]);
            a.w = __float_as_uint(Ps[(pr + 8) * AP + kc * 8 + q + 4]);
            #pragma unroll
            for (int nd = 0; nd < 8; nd++) {
                uint2 bb;
                bb.x = __float_as_uint(Vt[(nd * 8 + g) * AP + kc * 8 + q]);
                bb.y = __float_as_uint(Vt[(nd * 8 + g) * AP + kc * 8 + q + 4]);
                mma_tf32(o[nd], a, bb);
            }
        }
    }

    // ---- epilogue: normalize, store (heads interleaved) ----
    float* ob = out + ((size_t)(b * S) + qt * 128) * 1024 + h * 64;
    const float inv0 = 1.0f / l0, inv1 = 1.0f / l1;
    #pragma unroll
    for (int nd = 0; nd < 8; nd++) {
        const int c = nd * 8 + 2 * q;
        float2 v0, v1;
        v0.x = o[nd][0] * inv0; v0.y = o[nd][1] * inv0;
        v1.x = o[nd][2] * inv1; v1.y = o[nd][3] * inv1;
        *(float2*)&ob[(size_t)pr * 1024 + c]       = v0;
        *(float2*)&ob[(size_t)(pr + 8) * 1024 + c] = v1;
    }
}

// ---------------- launch -------------------------------------------------
extern "C" void kernel_launch(void* const* d_in, const int* in_sizes, int n_in,
                              void* d_out, int out_size)
{
    const float* x      = (const float*)d_in[0];   // [4,2048,1024]
    const float* W_qkv  = (const float*)d_in[1];   // [1024,3072]
    const float* W_proj = (const float*)d_in[2];   // [1024,1024]
    const float* b_proj = (const float*)d_in[3];   // [1024]
    float* out = (float*)d_out;

    float *qkv = nullptr, *att = nullptr, *wqT = nullptr, *wpT = nullptr;
    cudaGetSymbolAddress((void**)&qkv, g_qkv);
    cudaGetSymbolAddress((void**)&att, g_att);
    cudaGetSymbolAddress((void**)&wqT, g_wqT);
    cudaGetSymbolAddress((void**)&wpT, g_wpT);

    cudaFuncSetAttribute(attn_tc,
                         cudaFuncAttributeMaxDynamicSharedMemorySize, ATTN_SMEM);

    const int M = 8192;

    // 0) transpose + tf32-round weights
    transpose_rna<<<dim3(3072 / 32, 1024 / 32), 256>>>(W_qkv, wqT, 1024, 3072);
    transpose_rna<<<dim3(1024 / 32, 1024 / 32), 256>>>(W_proj, wpT, 1024, 1024);

    // 1) qkv = x @ W_qkv  (tf32 mma.sync)
    gemm_mma<<<dim3(3072 / 128, M / 128), 256>>>(x, wqT, nullptr, qkv,
                                                 M, 3072, 1024);
    // 2) causal flash attention (tf32 mma.sync)
    attn_tc<<<dim3(16, 16, 4), 256, ATTN_SMEM>>>(qkv, att);

    // 3) out = att @ W_proj + b_proj
    gemm_mma<<<dim3(1024 / 128, M / 128), 256>>>(att, wpT, b_proj, out,
                                                 M, 1024, 1024);
}

// round 7
// speedup vs baseline: 2.2202x; 1.2957x over previous
#include <cuda_runtime.h>
#include <cstdint>

// ---------------- scratch (no allocation allowed) ----------------
__device__ float g_qkv[8192 * 3072];   // [B*S, 3*EMB]
__device__ float g_att[8192 * 1024];   // [B*S, EMB]
__device__ float g_wqT[3072 * 1024];   // W_qkv transposed [N,K], tf32-rounded
__device__ float g_wpT[1024 * 1024];   // W_proj transposed [N,K], tf32-rounded

// ---------------- helpers --------------------------------------
__device__ __forceinline__ uint32_t f2tf32(float v) {
    uint32_t u;
    asm("cvt.rna.tf32.f32 %0, %1;" : "=r"(u) : "f"(v));
    return u;
}
__device__ __forceinline__ float tf32f(float v) {
    return __uint_as_float(f2tf32(v));
}

__device__ __forceinline__ void mma_tf32(float c[4], const uint4& a, const uint2& b) {
    asm volatile(
        "mma.sync.aligned.m16n8k8.row.col.f32.tf32.tf32.f32 "
        "{%0,%1,%2,%3}, {%4,%5,%6,%7}, {%8,%9}, {%0,%1,%2,%3};"
        : "+f"(c[0]), "+f"(c[1]), "+f"(c[2]), "+f"(c[3])
        : "r"(a.x), "r"(a.y), "r"(a.z), "r"(a.w), "r"(b.x), "r"(b.y));
}

// ---------------- weight transpose + tf32 rounding ------------------------
__global__ __launch_bounds__(256) void transpose_rna(
    const float* __restrict__ in, float* __restrict__ out, int R, int C)
{
    __shared__ float t[32][33];
    const int c0 = blockIdx.x * 32, r0 = blockIdx.y * 32;
    const int x = threadIdx.x & 31, y = threadIdx.x >> 5;  // 32x8
    #pragma unroll
    for (int i = 0; i < 32; i += 8) {
        float v = in[(size_t)(r0 + y + i) * C + c0 + x];
        t[y + i][x] = tf32f(v);
    }
    __syncthreads();
    #pragma unroll
    for (int i = 0; i < 32; i += 8)
        out[(size_t)(c0 + y + i) * R + r0 + x] = t[x][y + i];
}

// ---------------- tf32 mma.sync GEMM: C[M,N] = A[M,K] @ BT[N,K]^T (+bias) -
// 128x128 CTA tile, BK=16, 256 threads = 4x2 warp grid, warp tile 32x64.
// Direct-to-fragment staging: each thread gathers its own fragment elements
// from gmem and writes ONE conflict-free vector STS. Double-buffered smem,
// register prefetch, 1 syncthreads per k-iteration.
__global__ __launch_bounds__(256, 2) void gemm_mma(
    const float* __restrict__ A, const float* __restrict__ BT,
    const float* __restrict__ bias, float* __restrict__ C,
    int M, int N, int K)
{
    // As4[buf][ (ks*8 + mtile)*32 + lane ] : A-frag uint4 (reg order a0..a3)
    // Bs2[buf][ (ks*16 + ntile)*32 + lane ] : B-frag uint2
    __shared__ uint4 As4[2][512];
    __shared__ uint2 Bs2[2][1024];

    const int tid  = threadIdx.x;
    const int wid  = tid >> 5, lane = tid & 31;
    const int wr   = wid & 3;            // warp row (m-tiles 2wr, 2wr+1)
    const int wc   = wid >> 2;           // warp col (n-tiles wc*8..+7)
    const int g    = lane >> 2, q = lane & 3;
    const int brow = blockIdx.y * 128, bcol = blockIdx.x * 128;

    // staging roles: warp id picks the m-tile / n-tile pair this thread feeds
    const float* Ar0 = A  + (size_t)(brow + wid * 16 + g) * K + q;
    const float* Ar1 = Ar0 + (size_t)8 * K;
    const float* Br0 = BT + (size_t)(bcol + wid * 8 + g) * K + q;
    const float* Br1 = BT + (size_t)(bcol + (wid + 8) * 8 + g) * K + q;

    float acc[2][8][4];
    #pragma unroll
    for (int i = 0; i < 2; i++)
        #pragma unroll
        for (int j = 0; j < 8; j++)
            #pragma unroll
            for (int e = 0; e < 4; e++) acc[i][j][e] = 0.0f;

    float rA[2][4], rB[2][4];

    auto loads = [&](int kt) {
        #pragma unroll
        for (int ks = 0; ks < 2; ks++) {
            const int c = kt + ks * 8;
            rA[ks][0] = Ar0[c];     rA[ks][1] = Ar1[c];
            rA[ks][2] = Ar0[c + 4]; rA[ks][3] = Ar1[c + 4];
            rB[ks][0] = Br0[c];     rB[ks][1] = Br0[c + 4];
            rB[ks][2] = Br1[c];     rB[ks][3] = Br1[c + 4];
        }
    };
    auto stores = [&](int buf) {
        #pragma unroll
        for (int ks = 0; ks < 2; ks++) {
            As4[buf][(ks * 8 + wid) * 32 + lane] =
                make_uint4(f2tf32(rA[ks][0]), f2tf32(rA[ks][1]),
                           f2tf32(rA[ks][2]), f2tf32(rA[ks][3]));
            Bs2[buf][(ks * 16 + wid) * 32 + lane] =
                make_uint2(f2tf32(rB[ks][0]), f2tf32(rB[ks][1]));
            Bs2[buf][(ks * 16 + wid + 8) * 32 + lane] =
                make_uint2(f2tf32(rB[ks][2]), f2tf32(rB[ks][3]));
        }
    };

    const int iters = K >> 4;
    loads(0);
    stores(0);
    __syncthreads();

    for (int it = 0; it < iters; it++) {
        if (it + 1 < iters) loads((it + 1) << 4);

        const int buf = it & 1;
        #pragma unroll
        for (int s = 0; s < 2; s++) {
            uint4 af[2];
            af[0] = As4[buf][(s * 8 + wr * 2 + 0) * 32 + lane];
            af[1] = As4[buf][(s * 8 + wr * 2 + 1) * 32 + lane];
            uint2 bf[8];
            #pragma unroll
            for (int j = 0; j < 8; j++)
                bf[j] = Bs2[buf][(s * 16 + wc * 8 + j) * 32 + lane];
            #pragma unroll
            for (int i = 0; i < 2; i++)
                #pragma unroll
                for (int j = 0; j < 8; j++)
                    mma_tf32(acc[i][j], af[i], bf[j]);
        }

        if (it + 1 < iters) stores((it + 1) & 1);
        __syncthreads();
    }

    const int gg = lane >> 2, qq = lane & 3;
    #pragma unroll
    for (int i = 0; i < 2; i++) {
        const int row0 = brow + (wr * 2 + i) * 16 + gg;
        #pragma unroll
        for (int j = 0; j < 8; j++) {
            const int col = bcol + wc * 64 + j * 8 + qq * 2;
            float b0 = 0.0f, b1 = 0.0f;
            if (bias) { b0 = bias[col]; b1 = bias[col + 1]; }
            float2 v0, v1;
            v0.x = acc[i][j][0] + b0; v0.y = acc[i][j][1] + b1;
            v1.x = acc[i][j][2] + b0; v1.y = acc[i][j][3] + b1;
            *(float2*)&C[(size_t)row0 * N + col]       = v0;
            *(float2*)&C[(size_t)(row0 + 8) * N + col] = v1;
        }
    }
}

// ---------------- tf32 mma flash attention, BQ=128, BK=64 -----------------
// 256 threads = 8 warps; warp w owns q rows [w*16, w*16+16).
// Q/K: row-major pitch-68 tiles, explicit per-lane fragment gathers (verified).
// V: row-major (conflict-free float4 staging). P stays in registers: the
// softmaxed S C-fragment is reused as the PV A-fragment under the kv
// permutation sigma: slot q <-> old col 2q, slot q+4 <-> old col 2q+1,
// with V B-frag rows fetched at old rows 8*kc+2q, 8*kc+2q+1.
static constexpr int AP = 68;
static constexpr int ATTN_SMEM = (128 + 64 + 64) * AP * 4;

__global__ __launch_bounds__(256, 2) void attn_tc(
    const float* __restrict__ qkv, float* __restrict__ out)
{
    extern __shared__ float sm[];
    float* Qs = sm;                       // 128*AP
    float* Ks = Qs + 128 * AP;            // 64*AP
    float* Vs = Ks + 64 * AP;             // 64*AP (row-major kv x d)

    const int qt = (int)gridDim.x - 1 - (int)blockIdx.x;  // heavy tiles first
    const int h  = blockIdx.y;
    const int b  = blockIdx.z;
    const int tid = threadIdx.x, w = tid >> 5, lane = tid & 31;
    const int g = lane >> 2, q = lane & 3;
    const int S = 2048, D3 = 3072;

    // ---- stage Q once (row-major, scaled by 1/8, tf32-rounded) ----
    const float* Qb = qkv + ((size_t)(b * S) + qt * 128) * D3 + h * 64;
    for (int i = tid; i < 128 * 16; i += 256) {
        const int r = i >> 4, c4 = (i & 15) << 2;
        float4 v = *(const float4*)(Qb + (size_t)r * D3 + c4);
        float4 o4;
        o4.x = tf32f(v.x * 0.125f); o4.y = tf32f(v.y * 0.125f);
        o4.z = tf32f(v.z * 0.125f); o4.w = tf32f(v.w * 0.125f);
        *(float4*)&Qs[r * AP + c4] = o4;
    }

    float s[8][4], o[8][4];
    float m0 = -1e30f, m1 = -1e30f, l0 = 0.0f, l1 = 0.0f;
    #pragma unroll
    for (int j = 0; j < 8; j++)
        #pragma unroll
        for (int e = 0; e < 4; e++) o[j][e] = 0.0f;

    const int pr = w * 16 + g;   // this lane's q row (and +8)

    const int ktmax = 2 * qt + 1;
    for (int kt = 0; kt <= ktmax; kt++) {
        __syncthreads();  // prior-iter Ks/Vs reads complete
        // ---- stage K tile (row-major kv x d) ----
        const float* Kb = qkv + ((size_t)(b * S) + kt * 64) * D3 + 1024 + h * 64;
        for (int i = tid; i < 64 * 16; i += 256) {
            const int r = i >> 4, c4 = (i & 15) << 2;
            float4 v = *(const float4*)(Kb + (size_t)r * D3 + c4);
            float4 o4;
            o4.x = tf32f(v.x); o4.y = tf32f(v.y);
            o4.z = tf32f(v.z); o4.w = tf32f(v.w);
            *(float4*)&Ks[r * AP + c4] = o4;
        }
        // ---- stage V tile (row-major kv x d, conflict-free) ----
        const float* Vb = qkv + ((size_t)(b * S) + kt * 64) * D3 + 2048 + h * 64;
        for (int i = tid; i < 64 * 16; i += 256) {
            const int r = i >> 4, c4 = (i & 15) << 2;
            float4 v = *(const float4*)(Vb + (size_t)r * D3 + c4);
            float4 o4;
            o4.x = tf32f(v.x); o4.y = tf32f(v.y);
            o4.z = tf32f(v.z); o4.w = tf32f(v.w);
            *(float4*)&Vs[r * AP + c4] = o4;
        }
        __syncthreads();

        // ---- S = (Q/8) @ K^T : per-lane explicit fragment gathers ----
        #pragma unroll
        for (int j = 0; j < 8; j++)
            #pragma unroll
            for (int e = 0; e < 4; e++) s[j][e] = 0.0f;

        #pragma unroll
        for (int kc = 0; kc < 8; kc++) {
            uint4 a;
            a.x = __float_as_uint(Qs[pr * AP + kc * 8 + q]);
            a.y = __float_as_uint(Qs[(pr + 8) * AP + kc * 8 + q]);
            a.z = __float_as_uint(Qs[pr * AP + kc * 8 + q + 4]);
            a.w = __float_as_uint(Qs[(pr + 8) * AP + kc * 8 + q + 4]);
            #pragma unroll
            for (int nt = 0; nt < 8; nt++) {
                uint2 bb;
                bb.x = __float_as_uint(Ks[(nt * 8 + g) * AP + kc * 8 + q]);
                bb.y = __float_as_uint(Ks[(nt * 8 + g) * AP + kc * 8 + q + 4]);
                mma_tf32(s[nt], a, bb);
            }
        }

        // ---- causal mask on diagonal tiles ----
        if (kt >= 2 * qt) {
            const int r0  = qt * 128 + pr;
            const int kvb = kt * 64 + 2 * q;
            #pragma unroll
            for (int nt = 0; nt < 8; nt++) {
                const int c = kvb + nt * 8;
                if (c     > r0)     s[nt][0] = -1e30f;
                if (c + 1 > r0)     s[nt][1] = -1e30f;
                if (c     > r0 + 8) s[nt][2] = -1e30f;
                if (c + 1 > r0 + 8) s[nt][3] = -1e30f;
            }
        }

        // ---- online softmax on C-frags (rows g / g+8) ----
        float mx0 = -1e30f, mx1 = -1e30f;
        #pragma unroll
        for (int nt = 0; nt < 8; nt++) {
            mx0 = fmaxf(mx0, fmaxf(s[nt][0], s[nt][1]));
            mx1 = fmaxf(mx1, fmaxf(s[nt][2], s[nt][3]));
        }
        mx0 = fmaxf(mx0, __shfl_xor_sync(0xffffffffu, mx0, 1, 4));
        mx0 = fmaxf(mx0, __shfl_xor_sync(0xffffffffu, mx0, 2, 4));
        mx1 = fmaxf(mx1, __shfl_xor_sync(0xffffffffu, mx1, 1, 4));
        mx1 = fmaxf(mx1, __shfl_xor_sync(0xffffffffu, mx1, 2, 4));

        const float mn0 = fmaxf(m0, mx0), mn1 = fmaxf(m1, mx1);
        const float al0 = __expf(m0 - mn0), al1 = __expf(m1 - mn1);
        m0 = mn0; m1 = mn1;

        float rs0 = 0.0f, rs1 = 0.0f;
        #pragma unroll
        for (int nt = 0; nt < 8; nt++) {
            s[nt][0] = __expf(s[nt][0] - mn0); rs0 += s[nt][0];
            s[nt][1] = __expf(s[nt][1] - mn0); rs0 += s[nt][1];
            s[nt][2] = __expf(s[nt][2] - mn1); rs1 += s[nt][2];
            s[nt][3] = __expf(s[nt][3] - mn1); rs1 += s[nt][3];
        }
        rs0 += __shfl_xor_sync(0xffffffffu, rs0, 1, 4);
        rs0 += __shfl_xor_sync(0xffffffffu, rs0, 2, 4);
        rs1 += __shfl_xor_sync(0xffffffffu, rs1, 1, 4);
        rs1 += __shfl_xor_sync(0xffffffffu, rs1, 2, 4);
        l0 = l0 * al0 + rs0;
        l1 = l1 * al1 + rs1;

        #pragma unroll
        for (int j = 0; j < 8; j++) {
            o[j][0] *= al0; o[j][1] *= al0;
            o[j][2] *= al1; o[j][3] *= al1;
        }

        // ---- O += P @ V : P C-frag reused as A-frag via sigma permutation --
        // kstep kc: slot q <-> old col kc*8+2q (s[kc][0]/[2]),
        //           slot q+4 <-> old col kc*8+2q+1 (s[kc][1]/[3]);
        // V B-frag rows fetched at old rows kc*8+2q, kc*8+2q+1.
        #pragma unroll
        for (int kc = 0; kc < 8; kc++) {
            uint4 a;
            a.x = f2tf32(s[kc][0]);
            a.y = f2tf32(s[kc][2]);
            a.z = f2tf32(s[kc][1]);
            a.w = f2tf32(s[kc][3]);
            const float* vr = &Vs[(kc * 8 + 2 * q) * AP];
            #pragma unroll
            for (int nd = 0; nd < 8; nd++) {
                uint2 bb;
                bb.x = __float_as_uint(vr[nd * 8 + g]);
                bb.y = __float_as_uint(vr[AP + nd * 8 + g]);
                mma_tf32(o[nd], a, bb);
            }
        }
    }

    // ---- epilogue: normalize, store (heads interleaved) ----
    float* ob = out + ((size_t)(b * S) + qt * 128) * 1024 + h * 64;
    const float inv0 = 1.0f / l0, inv1 = 1.0f / l1;
    #pragma unroll
    for (int nd = 0; nd < 8; nd++) {
        const int c = nd * 8 + 2 * q;
        float2 v0, v1;
        v0.x = o[nd][0] * inv0; v0.y = o[nd][1] * inv0;
        v1.x = o[nd][2] * inv1; v1.y = o[nd][3] * inv1;
        *(float2*)&ob[(size_t)pr * 1024 + c]       = v0;
        *(float2*)&ob[(size_t)(pr + 8) * 1024 + c] = v1;
    }
}

// ---------------- launch -------------------------------------------------
extern "C" void kernel_launch(void* const* d_in, const int* in_sizes, int n_in,
                              void* d_out, int out_size)
{
    const float* x      = (const float*)d_in[0];   // [4,2048,1024]
    const float* W_qkv  = (const float*)d_in[1];   // [1024,3072]
    const float* W_proj = (const float*)d_in[2];   // [1024,1024]
    const float* b_proj = (const float*)d_in[3];   // [1024]
    float* out = (float*)d_out;

    float *qkv = nullptr, *att = nullptr, *wqT = nullptr, *wpT = nullptr;
    cudaGetSymbolAddress((void**)&qkv, g_qkv);
    cudaGetSymbolAddress((void**)&att, g_att);
    cudaGetSymbolAddress((void**)&wqT, g_wqT);
    cudaGetSymbolAddress((void**)&wpT, g_wpT);

    cudaFuncSetAttribute(attn_tc,
                         cudaFuncAttributeMaxDynamicSharedMemorySize, ATTN_SMEM);

    const int M = 8192;

    // 0) transpose + tf32-round weights
    transpose_rna<<<dim3(3072 / 32, 1024 / 32), 256>>>(W_qkv, wqT, 1024, 3072);
    transpose_rna<<<dim3(1024 / 32, 1024 / 32), 256>>>(W_proj, wpT, 1024, 1024);

    // 1) qkv = x @ W_qkv  (tf32 mma.sync)
    gemm_mma<<<dim3(3072 / 128, M / 128), 256>>>(x, wqT, nullptr, qkv,
                                                 M, 3072, 1024);
    // 2) causal flash attention (tf32 mma.sync)
    attn_tc<<<dim3(16, 16, 4), 256, ATTN_SMEM>>>(qkv, att);

    // 3) out = att @ W_proj + b_proj
    gemm_mma<<<dim3(1024 / 128, M / 128), 256>>>(att, wpT, b_proj, out,
                                                 M, 1024, 1024);
}

// round 8
// speedup vs baseline: 2.6645x; 1.2001x over previous
#include <cuda_runtime.h>
#include <cstdint>

// ---------------- scratch (no allocation allowed) ----------------
__device__ float g_qkv[8192 * 3072];   // [B*S, 3*EMB]
__device__ float g_att[8192 * 1024];   // [B*S, EMB] (tf32-rounded by attn epilogue)
__device__ float g_xr[8192 * 1024];    // x tf32-rounded
__device__ float g_wqT[3072 * 1024];   // W_qkv^T [N,K], tf32-rounded
__device__ float g_wpT[1024 * 1024];   // W_proj^T [N,K], tf32-rounded

// ---------------- helpers --------------------------------------
__device__ __forceinline__ uint32_t f2tf32(float v) {
    uint32_t u;
    asm("cvt.rna.tf32.f32 %0, %1;" : "=r"(u) : "f"(v));
    return u;
}
__device__ __forceinline__ float tf32f(float v) {
    return __uint_as_float(f2tf32(v));
}
__device__ __forceinline__ uint32_t cvta_smem(const void* p) {
    uint32_t a;
    asm("{ .reg .u64 t; cvta.to.shared.u64 t, %1; cvt.u32.u64 %0, t; }"
        : "=r"(a) : "l"(p));
    return a;
}
__device__ __forceinline__ void cp16(uint32_t dst, const void* src) {
    asm volatile("cp.async.cg.shared.global [%0], [%1], 16;"
                 :: "r"(dst), "l"(src) : "memory");
}

__device__ __forceinline__ void mma_tf32(float c[4], const uint4& a, const uint2& b) {
    asm volatile(
        "mma.sync.aligned.m16n8k8.row.col.f32.tf32.tf32.f32 "
        "{%0,%1,%2,%3}, {%4,%5,%6,%7}, {%8,%9}, {%0,%1,%2,%3};"
        : "+f"(c[0]), "+f"(c[1]), "+f"(c[2]), "+f"(c[3])
        : "r"(a.x), "r"(a.y), "r"(a.z), "r"(a.w), "r"(b.x), "r"(b.y));
}

// ---------------- rna-round a float buffer (for x) -------------------------
__global__ __launch_bounds__(256) void round_rna_vec(
    const float4* __restrict__ in, float4* __restrict__ out, int n4)
{
    int i = blockIdx.x * blockDim.x + threadIdx.x;
    if (i < n4) {
        float4 v = in[i];
        v.x = tf32f(v.x); v.y = tf32f(v.y);
        v.z = tf32f(v.z); v.w = tf32f(v.w);
        out[i] = v;
    }
}

// ---------------- weight transpose + tf32 rounding ------------------------
__global__ __launch_bounds__(256) void transpose_rna(
    const float* __restrict__ in, float* __restrict__ out, int R, int C)
{
    __shared__ float t[32][33];
    const int c0 = blockIdx.x * 32, r0 = blockIdx.y * 32;
    const int x = threadIdx.x & 31, y = threadIdx.x >> 5;  // 32x8
    #pragma unroll
    for (int i = 0; i < 32; i += 8) {
        float v = in[(size_t)(r0 + y + i) * C + c0 + x];
        t[y + i][x] = tf32f(v);
    }
    __syncthreads();
    #pragma unroll
    for (int i = 0; i < 32; i += 8)
        out[(size_t)(c0 + y + i) * R + r0 + x] = t[x][y + i];
}

// ---------------- cp.async-pipelined tf32 GEMM ----------------------------
// C[M,N] = A[M,K] @ BT[N,K]^T (+bias). A, BT MUST be tf32-pre-rounded (HMMA
// truncation is then exact). 128x128 CTA tile, BK=16, 256 thr = 4x2 warps.
// Row-major smem tiles, pitch 20 floats (banks 20g+q mod 32 all-distinct ->
// conflict-free fragment gathers). 4-stage cp.async pipeline, wait_group 2.
static constexpr int GP = 20;                       // smem row pitch (floats)
static constexpr int GSTAGE_FLOATS = 2 * 128 * GP;  // A tile + B tile = 5120
static constexpr int GEMM_SMEM = 4 * GSTAGE_FLOATS * 4;  // 81920 bytes

__global__ __launch_bounds__(256, 2) void gemm_cp(
    const float* __restrict__ A, const float* __restrict__ BT,
    const float* __restrict__ bias, float* __restrict__ C,
    int M, int N, int K)
{
    extern __shared__ float gsm[];
    const uint32_t sbase = cvta_smem(gsm);

    const int tid  = threadIdx.x;
    const int wid  = tid >> 5, lane = tid & 31;
    const int wr   = wid & 3;            // warp row (m-tiles 2wr, 2wr+1)
    const int wc   = wid >> 2;           // warp col (n-tiles wc*8..+7)
    const int g    = lane >> 2, q = lane & 3;
    const int brow = blockIdx.y * 128, bcol = blockIdx.x * 128;

    // cp.async roles: thread -> tile row cr, 32B half cc
    const int cr = tid >> 1;
    const int cc = (tid & 1) * 32;       // byte offset within 64B row chunk
    const char* Asrc = (const char*)(A  + (size_t)(brow + cr) * K) + cc;
    const char* Bsrc = (const char*)(BT + (size_t)(bcol + cr) * K) + cc;

    const int iters = K >> 4;

    auto issue = [&](int it) {
        if (it < iters) {
            const uint32_t st = (uint32_t)(it & 3) * (GSTAGE_FLOATS * 4);
            const uint32_t da = sbase + st + cr * (GP * 4) + cc;
            const uint32_t db = da + 128 * GP * 4;
            const char* sa = Asrc + (size_t)it * 64;
            const char* sb = Bsrc + (size_t)it * 64;
            cp16(da,      sa);
            cp16(da + 16, sa + 16);
            cp16(db,      sb);
            cp16(db + 16, sb + 16);
        }
        asm volatile("cp.async.commit_group;" ::: "memory");
    };

    float acc[2][8][4];
    #pragma unroll
    for (int i = 0; i < 2; i++)
        #pragma unroll
        for (int j = 0; j < 8; j++)
            #pragma unroll
            for (int e = 0; e < 4; e++) acc[i][j][e] = 0.0f;

    issue(0); issue(1); issue(2);

    for (int it = 0; it < iters; it++) {
        asm volatile("cp.async.wait_group 2;" ::: "memory");
        __syncthreads();
        issue(it + 3);

        const float* As = gsm + (it & 3) * GSTAGE_FLOATS;
        const float* Bs = As + 128 * GP;

        #pragma unroll
        for (int s = 0; s < 2; s++) {
            uint4 af[2];
            #pragma unroll
            for (int i = 0; i < 2; i++) {
                const int row = (wr * 2 + i) * 16;
                af[i].x = __float_as_uint(As[(row + g) * GP + s * 8 + q]);
                af[i].y = __float_as_uint(As[(row + 8 + g) * GP + s * 8 + q]);
                af[i].z = __float_as_uint(As[(row + g) * GP + s * 8 + q + 4]);
                af[i].w = __float_as_uint(As[(row + 8 + g) * GP + s * 8 + q + 4]);
            }
            uint2 bf[8];
            #pragma unroll
            for (int j = 0; j < 8; j++) {
                const int row = (wc * 64 + j * 8 + g) * GP;
                bf[j].x = __float_as_uint(Bs[row + s * 8 + q]);
                bf[j].y = __float_as_uint(Bs[row + s * 8 + q + 4]);
            }
            #pragma unroll
            for (int i = 0; i < 2; i++)
                #pragma unroll
                for (int j = 0; j < 8; j++)
                    mma_tf32(acc[i][j], af[i], bf[j]);
        }
    }

    #pragma unroll
    for (int i = 0; i < 2; i++) {
        const int row0 = brow + (wr * 2 + i) * 16 + g;
        #pragma unroll
        for (int j = 0; j < 8; j++) {
            const int col = bcol + wc * 64 + j * 8 + q * 2;
            float b0 = 0.0f, b1 = 0.0f;
            if (bias) { b0 = bias[col]; b1 = bias[col + 1]; }
            float2 v0, v1;
            v0.x = acc[i][j][0] + b0; v0.y = acc[i][j][1] + b1;
            v1.x = acc[i][j][2] + b0; v1.y = acc[i][j][3] + b1;
            *(float2*)&C[(size_t)row0 * N + col]       = v0;
            *(float2*)&C[(size_t)(row0 + 8) * N + col] = v1;
        }
    }
}

// ---------------- tf32 mma flash attention, BQ=128, BK=64 -----------------
// (unchanged from R7 except epilogue tf32-rounds the output so the proj GEMM
// can consume it via cp.async + HMMA truncation bit-exactly.)
static constexpr int AP = 68;
static constexpr int ATTN_SMEM = (128 + 64 + 64) * AP * 4;

__global__ __launch_bounds__(256, 2) void attn_tc(
    const float* __restrict__ qkv, float* __restrict__ out)
{
    extern __shared__ float sm[];
    float* Qs = sm;                       // 128*AP
    float* Ks = Qs + 128 * AP;            // 64*AP
    float* Vs = Ks + 64 * AP;             // 64*AP (row-major kv x d)

    const int qt = (int)gridDim.x - 1 - (int)blockIdx.x;  // heavy tiles first
    const int h  = blockIdx.y;
    const int b  = blockIdx.z;
    const int tid = threadIdx.x, w = tid >> 5, lane = tid & 31;
    const int g = lane >> 2, q = lane & 3;
    const int S = 2048, D3 = 3072;

    const float* Qb = qkv + ((size_t)(b * S) + qt * 128) * D3 + h * 64;
    for (int i = tid; i < 128 * 16; i += 256) {
        const int r = i >> 4, c4 = (i & 15) << 2;
        float4 v = *(const float4*)(Qb + (size_t)r * D3 + c4);
        float4 o4;
        o4.x = tf32f(v.x * 0.125f); o4.y = tf32f(v.y * 0.125f);
        o4.z = tf32f(v.z * 0.125f); o4.w = tf32f(v.w * 0.125f);
        *(float4*)&Qs[r * AP + c4] = o4;
    }

    float s[8][4], o[8][4];
    float m0 = -1e30f, m1 = -1e30f, l0 = 0.0f, l1 = 0.0f;
    #pragma unroll
    for (int j = 0; j < 8; j++)
        #pragma unroll
        for (int e = 0; e < 4; e++) o[j][e] = 0.0f;

    const int pr = w * 16 + g;

    const int ktmax = 2 * qt + 1;
    for (int kt = 0; kt <= ktmax; kt++) {
        __syncthreads();
        const float* Kb = qkv + ((size_t)(b * S) + kt * 64) * D3 + 1024 + h * 64;
        for (int i = tid; i < 64 * 16; i += 256) {
            const int r = i >> 4, c4 = (i & 15) << 2;
            float4 v = *(const float4*)(Kb + (size_t)r * D3 + c4);
            float4 o4;
            o4.x = tf32f(v.x); o4.y = tf32f(v.y);
            o4.z = tf32f(v.z); o4.w = tf32f(v.w);
            *(float4*)&Ks[r * AP + c4] = o4;
        }
        const float* Vb = qkv + ((size_t)(b * S) + kt * 64) * D3 + 2048 + h * 64;
        for (int i = tid; i < 64 * 16; i += 256) {
            const int r = i >> 4, c4 = (i & 15) << 2;
            float4 v = *(const float4*)(Vb + (size_t)r * D3 + c4);
            float4 o4;
            o4.x = tf32f(v.x); o4.y = tf32f(v.y);
            o4.z = tf32f(v.z); o4.w = tf32f(v.w);
            *(float4*)&Vs[r * AP + c4] = o4;
        }
        __syncthreads();

        #pragma unroll
        for (int j = 0; j < 8; j++)
            #pragma unroll
            for (int e = 0; e < 4; e++) s[j][e] = 0.0f;

        #pragma unroll
        for (int kc = 0; kc < 8; kc++) {
            uint4 a;
            a.x = __float_as_uint(Qs[pr * AP + kc * 8 + q]);
            a.y = __float_as_uint(Qs[(pr + 8) * AP + kc * 8 + q]);
            a.z = __float_as_uint(Qs[pr * AP + kc * 8 + q + 4]);
            a.w = __float_as_uint(Qs[(pr + 8) * AP + kc * 8 + q + 4]);
            #pragma unroll
            for (int nt = 0; nt < 8; nt++) {
                uint2 bb;
                bb.x = __float_as_uint(Ks[(nt * 8 + g) * AP + kc * 8 + q]);
                bb.y = __float_as_uint(Ks[(nt * 8 + g) * AP + kc * 8 + q + 4]);
                mma_tf32(s[nt], a, bb);
            }
        }

        if (kt >= 2 * qt) {
            const int r0  = qt * 128 + pr;
            const int kvb = kt * 64 + 2 * q;
            #pragma unroll
            for (int nt = 0; nt < 8; nt++) {
                const int c = kvb + nt * 8;
                if (c     > r0)     s[nt][0] = -1e30f;
                if (c + 1 > r0)     s[nt][1] = -1e30f;
                if (c     > r0 + 8) s[nt][2] = -1e30f;
                if (c + 1 > r0 + 8) s[nt][3] = -1e30f;
            }
        }

        float mx0 = -1e30f, mx1 = -1e30f;
        #pragma unroll
        for (int nt = 0; nt < 8; nt++) {
            mx0 = fmaxf(mx0, fmaxf(s[nt][0], s[nt][1]));
            mx1 = fmaxf(mx1, fmaxf(s[nt][2], s[nt][3]));
        }
        mx0 = fmaxf(mx0, __shfl_xor_sync(0xffffffffu, mx0, 1, 4));
        mx0 = fmaxf(mx0, __shfl_xor_sync(0xffffffffu, mx0, 2, 4));
        mx1 = fmaxf(mx1, __shfl_xor_sync(0xffffffffu, mx1, 1, 4));
        mx1 = fmaxf(mx1, __shfl_xor_sync(0xffffffffu, mx1, 2, 4));

        const float mn0 = fmaxf(m0, mx0), mn1 = fmaxf(m1, mx1);
        const float al0 = __expf(m0 - mn0), al1 = __expf(m1 - mn1);
        m0 = mn0; m1 = mn1;

        float rs0 = 0.0f, rs1 = 0.0f;
        #pragma unroll
        for (int nt = 0; nt < 8; nt++) {
            s[nt][0] = __expf(s[nt][0] - mn0); rs0 += s[nt][0];
            s[nt][1] = __expf(s[nt][1] - mn0); rs0 += s[nt][1];
            s[nt][2] = __expf(s[nt][2] - mn1); rs1 += s[nt][2];
            s[nt][3] = __expf(s[nt][3] - mn1); rs1 += s[nt][3];
        }
        rs0 += __shfl_xor_sync(0xffffffffu, rs0, 1, 4);
        rs0 += __shfl_xor_sync(0xffffffffu, rs0, 2, 4);
        rs1 += __shfl_xor_sync(0xffffffffu, rs1, 1, 4);
        rs1 += __shfl_xor_sync(0xffffffffu, rs1, 2, 4);
        l0 = l0 * al0 + rs0;
        l1 = l1 * al1 + rs1;

        #pragma unroll
        for (int j = 0; j < 8; j++) {
            o[j][0] *= al0; o[j][1] *= al0;
            o[j][2] *= al1; o[j][3] *= al1;
        }

        #pragma unroll
        for (int kc = 0; kc < 8; kc++) {
            uint4 a;
            a.x = f2tf32(s[kc][0]);
            a.y = f2tf32(s[kc][2]);
            a.z = f2tf32(s[kc][1]);
            a.w = f2tf32(s[kc][3]);
            const float* vr = &Vs[(kc * 8 + 2 * q) * AP];
            #pragma unroll
            for (int nd = 0; nd < 8; nd++) {
                uint2 bb;
                bb.x = __float_as_uint(vr[nd * 8 + g]);
                bb.y = __float_as_uint(vr[AP + nd * 8 + g]);
                mma_tf32(o[nd], a, bb);
            }
        }
    }

    // epilogue: normalize, tf32-round (pre-round for proj GEMM), store
    float* ob = out + ((size_t)(b * S) + qt * 128) * 1024 + h * 64;
    const float inv0 = 1.0f / l0, inv1 = 1.0f / l1;
    #pragma unroll
    for (int nd = 0; nd < 8; nd++) {
        const int c = nd * 8 + 2 * q;
        float2 v0, v1;
        v0.x = tf32f(o[nd][0] * inv0); v0.y = tf32f(o[nd][1] * inv0);
        v1.x = tf32f(o[nd][2] * inv1); v1.y = tf32f(o[nd][3] * inv1);
        *(float2*)&ob[(size_t)pr * 1024 + c]       = v0;
        *(float2*)&ob[(size_t)(pr + 8) * 1024 + c] = v1;
    }
}

// ---------------- launch -------------------------------------------------
extern "C" void kernel_launch(void* const* d_in, const int* in_sizes, int n_in,
                              void* d_out, int out_size)
{
    const float* x      = (const float*)d_in[0];   // [4,2048,1024]
    const float* W_qkv  = (const float*)d_in[1];   // [1024,3072]
    const float* W_proj = (const float*)d_in[2];   // [1024,1024]
    const float* b_proj = (const float*)d_in[3];   // [1024]
    float* out = (float*)d_out;

    float *qkv = nullptr, *att = nullptr, *xr = nullptr, *wqT = nullptr, *wpT = nullptr;
    cudaGetSymbolAddress((void**)&qkv, g_qkv);
    cudaGetSymbolAddress((void**)&att, g_att);
    cudaGetSymbolAddress((void**)&xr,  g_xr);
    cudaGetSymbolAddress((void**)&wqT, g_wqT);
    cudaGetSymbolAddress((void**)&wpT, g_wpT);

    cudaFuncSetAttribute(attn_tc,
                         cudaFuncAttributeMaxDynamicSharedMemorySize, ATTN_SMEM);
    cudaFuncSetAttribute(gemm_cp,
                         cudaFuncAttributeMaxDynamicSharedMemorySize, GEMM_SMEM);

    const int M = 8192;

    // 0) pre-round x; transpose+round weights
    round_rna_vec<<<(M * 1024 / 4 + 255) / 256, 256>>>(
        (const float4*)x, (float4*)xr, M * 1024 / 4);
    transpose_rna<<<dim3(3072 / 32, 1024 / 32), 256>>>(W_qkv, wqT, 1024, 3072);
    transpose_rna<<<dim3(1024 / 32, 1024 / 32), 256>>>(W_proj, wpT, 1024, 1024);

    // 1) qkv = x @ W_qkv  (cp.async tf32 pipeline)
    gemm_cp<<<dim3(3072 / 128, M / 128), 256, GEMM_SMEM>>>(
        xr, wqT, nullptr, qkv, M, 3072, 1024);

    // 2) causal flash attention (tf32 mma.sync)
    attn_tc<<<dim3(16, 16, 4), 256, ATTN_SMEM>>>(qkv, att);

    // 3) out = att @ W_proj + b_proj
    gemm_cp<<<dim3(1024 / 128, M / 128), 256, GEMM_SMEM>>>(
        att, wpT, b_proj, out, M, 1024, 1024);
}

// round 9
// speedup vs baseline: 3.2480x; 1.2190x over previous
#include <cuda_runtime.h>
#include <cstdint>

// ---------------- scratch (no allocation allowed) ----------------
__device__ float g_qkv[8192 * 3072];   // [B*S, 3*EMB], tf32-rounded by gemm epilogue
__device__ float g_att[8192 * 1024];   // [B*S, EMB], tf32-rounded by attn epilogue
__device__ float g_xr[8192 * 1024];    // x tf32-rounded
__device__ float g_wqT[3072 * 1024];   // W_qkv^T [N,K], tf32-rounded
__device__ float g_wpT[1024 * 1024];   // W_proj^T [N,K], tf32-rounded

// ---------------- helpers --------------------------------------
__device__ __forceinline__ uint32_t f2tf32(float v) {
    uint32_t u;
    asm("cvt.rna.tf32.f32 %0, %1;" : "=r"(u) : "f"(v));
    return u;
}
__device__ __forceinline__ float tf32f(float v) {
    return __uint_as_float(f2tf32(v));
}
__device__ __forceinline__ uint32_t cvta_smem(const void* p) {
    uint32_t a;
    asm("{ .reg .u64 t; cvta.to.shared.u64 t, %1; cvt.u32.u64 %0, t; }"
        : "=r"(a) : "l"(p));
    return a;
}
__device__ __forceinline__ void cp16(uint32_t dst, const void* src) {
    asm volatile("cp.async.cg.shared.global [%0], [%1], 16;"
                 :: "r"(dst), "l"(src) : "memory");
}
__device__ __forceinline__ uint4 ldsm_x4(uint32_t addr) {
    uint4 r;
    asm volatile("ldmatrix.sync.aligned.m8n8.x4.shared.b16 {%0,%1,%2,%3}, [%4];"
                 : "=r"(r.x), "=r"(r.y), "=r"(r.z), "=r"(r.w) : "r"(addr));
    return r;
}
__device__ __forceinline__ uint2 ldsm_x2(uint32_t addr) {
    uint2 r;
    asm volatile("ldmatrix.sync.aligned.m8n8.x2.shared.b16 {%0,%1}, [%2];"
                 : "=r"(r.x), "=r"(r.y) : "r"(addr));
    return r;
}

__device__ __forceinline__ void mma_tf32(float c[4], const uint4& a, const uint2& b) {
    asm volatile(
        "mma.sync.aligned.m16n8k8.row.col.f32.tf32.tf32.f32 "
        "{%0,%1,%2,%3}, {%4,%5,%6,%7}, {%8,%9}, {%0,%1,%2,%3};"
        : "+f"(c[0]), "+f"(c[1]), "+f"(c[2]), "+f"(c[3])
        : "r"(a.x), "r"(a.y), "r"(a.z), "r"(a.w), "r"(b.x), "r"(b.y));
}

// ---------------- rna-round a float buffer (for x) -------------------------
__global__ __launch_bounds__(256) void round_rna_vec(
    const float4* __restrict__ in, float4* __restrict__ out, int n4)
{
    int i = blockIdx.x * blockDim.x + threadIdx.x;
    if (i < n4) {
        float4 v = in[i];
        v.x = tf32f(v.x); v.y = tf32f(v.y);
        v.z = tf32f(v.z); v.w = tf32f(v.w);
        out[i] = v;
    }
}

// ---------------- weight transpose + tf32 rounding ------------------------
__global__ __launch_bounds__(256) void transpose_rna(
    const float* __restrict__ in, float* __restrict__ out, int R, int C)
{
    __shared__ float t[32][33];
    const int c0 = blockIdx.x * 32, r0 = blockIdx.y * 32;
    const int x = threadIdx.x & 31, y = threadIdx.x >> 5;  // 32x8
    #pragma unroll
    for (int i = 0; i < 32; i += 8) {
        float v = in[(size_t)(r0 + y + i) * C + c0 + x];
        t[y + i][x] = tf32f(v);
    }
    __syncthreads();
    #pragma unroll
    for (int i = 0; i < 32; i += 8)
        out[(size_t)(c0 + y + i) * R + r0 + x] = t[x][y + i];
}

// ---------------- cp.async-pipelined tf32 GEMM + ldmatrix ------------------
// C[M,N] = A[M,K] @ BT[N,K]^T (+bias). Inputs tf32-pre-rounded.
// 128x128 CTA tile, BK=16, 256 thr = 4x2 warps, 4-stage cp.async pipeline.
// Row-major smem tiles pitch 20 floats (80B rows -> ldmatrix phases hit
// distinct 4-bank groups). Fragments loaded via ldmatrix.
static constexpr int GP = 20;                       // smem row pitch (floats)
static constexpr int GSTAGE_FLOATS = 2 * 128 * GP;  // 5120 floats / stage
static constexpr int GEMM_SMEM = 4 * GSTAGE_FLOATS * 4;  // 81920 bytes

__global__ __launch_bounds__(256, 2) void gemm_cp(
    const float* __restrict__ A, const float* __restrict__ BT,
    const float* __restrict__ bias, float* __restrict__ C,
    int M, int N, int K, int round_out)
{
    extern __shared__ float gsm[];
    const uint32_t sbase = cvta_smem(gsm);

    const int tid  = threadIdx.x;
    const int wid  = tid >> 5, lane = tid & 31;
    const int wr   = wid & 3;            // warp row (m-tiles 2wr, 2wr+1)
    const int wc   = wid >> 2;           // warp col (n-tiles wc*8..+7)
    const int g    = lane >> 2, q = lane & 3;
    const int brow = blockIdx.y * 128, bcol = blockIdx.x * 128;

    // cp.async roles: thread -> tile row cr, 32B half cc
    const int cr = tid >> 1;
    const int cc = (tid & 1) * 32;
    const char* Asrc = (const char*)(A  + (size_t)(brow + cr) * K) + cc;
    const char* Bsrc = (const char*)(BT + (size_t)(bcol + cr) * K) + cc;

    const int iters = K >> 4;

    auto issue = [&](int it) {
        if (it < iters) {
            const uint32_t st = (uint32_t)(it & 3) * (GSTAGE_FLOATS * 4);
            const uint32_t da = sbase + st + cr * (GP * 4) + cc;
            const uint32_t db = da + 128 * GP * 4;
            const char* sa = Asrc + (size_t)it * 64;
            const char* sb = Bsrc + (size_t)it * 64;
            cp16(da,      sa);
            cp16(da + 16, sa + 16);
            cp16(db,      sb);
            cp16(db + 16, sb + 16);
        }
        asm volatile("cp.async.commit_group;" ::: "memory");
    };

    float acc[2][8][4];
    #pragma unroll
    for (int i = 0; i < 2; i++)
        #pragma unroll
        for (int j = 0; j < 8; j++)
            #pragma unroll
            for (int e = 0; e < 4; e++) acc[i][j][e] = 0.0f;

    // per-lane ldmatrix row offsets (bytes)
    const uint32_t aRowOff = (uint32_t)(lane & 15) * (GP * 4) + (lane >> 4) * 16;
    const uint32_t bRowOff = (uint32_t)(lane & 7) * (GP * 4) + ((lane >> 3) & 1) * 16;

    issue(0); issue(1); issue(2);

    for (int it = 0; it < iters; it++) {
        asm volatile("cp.async.wait_group 2;" ::: "memory");
        __syncthreads();
        issue(it + 3);

        const uint32_t stA = sbase + (uint32_t)(it & 3) * (GSTAGE_FLOATS * 4);
        const uint32_t stB = stA + 128 * GP * 4;

        #pragma unroll
        for (int s = 0; s < 2; s++) {
            uint4 af[2];
            #pragma unroll
            for (int i = 0; i < 2; i++)
                af[i] = ldsm_x4(stA + (uint32_t)((wr * 2 + i) * 16) * (GP * 4)
                                    + s * 32 + aRowOff);
            uint2 bf[8];
            #pragma unroll
            for (int j = 0; j < 8; j++)
                bf[j] = ldsm_x2(stB + (uint32_t)(wc * 64 + j * 8) * (GP * 4)
                                    + s * 32 + bRowOff);
            #pragma unroll
            for (int i = 0; i < 2; i++)
                #pragma unroll
                for (int j = 0; j < 8; j++)
                    mma_tf32(acc[i][j], af[i], bf[j]);
        }
    }

    #pragma unroll
    for (int i = 0; i < 2; i++) {
        const int row0 = brow + (wr * 2 + i) * 16 + g;
        #pragma unroll
        for (int j = 0; j < 8; j++) {
            const int col = bcol + wc * 64 + j * 8 + q * 2;
            float b0 = 0.0f, b1 = 0.0f;
            if (bias) { b0 = bias[col]; b1 = bias[col + 1]; }
            float2 v0, v1;
            v0.x = acc[i][j][0] + b0; v0.y = acc[i][j][1] + b1;
            v1.x = acc[i][j][2] + b0; v1.y = acc[i][j][3] + b1;
            if (round_out) {
                v0.x = tf32f(v0.x); v0.y = tf32f(v0.y);
                v1.x = tf32f(v1.x); v1.y = tf32f(v1.y);
            }
            *(float2*)&C[(size_t)row0 * N + col]       = v0;
            *(float2*)&C[(size_t)(row0 + 8) * N + col] = v1;
        }
    }
}

// ---------------- tf32 mma flash attention, BQ=128, BK=64 -----------------
// 256 threads = 8 warps; warp w owns q rows [w*16, w*16+16).
// Inputs (g_qkv) are tf32-pre-rounded -> raw cp.async staging, no cvt.
// Q staged once; K/V double-buffered cp.async pipeline. Q/K fragments via
// ldmatrix; V B-frags scalar (conflict-free); P reused in registers via
// sigma(kv) permutation. Scale 1/8 folded into S post-MMA (exact).
static constexpr int AP = 68;                 // pitch floats (272B rows)
static constexpr int QF = 128 * AP;           // Q floats
static constexpr int KVF = 64 * AP;           // K or V tile floats
static constexpr int ATTN_SMEM = (QF + 4 * KVF) * 4;  // 104448 bytes

__global__ __launch_bounds__(256, 2) void attn_tc(
    const float* __restrict__ qkv, float* __restrict__ out)
{
    extern __shared__ float sm[];
    const uint32_t sbase = cvta_smem(sm);

    const int qt = (int)gridDim.x - 1 - (int)blockIdx.x;  // heavy tiles first
    const int h  = blockIdx.y;
    const int b  = blockIdx.z;
    const int tid = threadIdx.x, w = tid >> 5, lane = tid & 31;
    const int g = lane >> 2, q = lane & 3;
    const int S = 2048, D3 = 3072;

    const uint32_t qBase  = sbase;                       // Q tile
    const uint32_t kBase0 = sbase + QF * 4;              // K buf0
    const uint32_t vBase0 = sbase + (QF + 2 * KVF) * 4;  // V buf0

    const float* Qb = qkv + ((size_t)(b * S) + qt * 128) * D3 + h * 64;
    const float* KVb = qkv + (size_t)(b * S) * D3 + 1024 + h * 64;

    // ---- stage Q raw (8 x cp16 per thread) ----
    {
        const int ch0 = tid * 8;
        #pragma unroll
        for (int i = 0; i < 8; i++) {
            const int ch = ch0 + i;                // 0..2047
            const int r = ch >> 4, c16 = ch & 15;  // row, 16B chunk
            cp16(qBase + (uint32_t)r * (AP * 4) + c16 * 16,
                 Qb + (size_t)r * D3 + c16 * 4);
        }
    }

    const int ktmax = 2 * qt + 1;

    // K/V staging: thread -> row tid>>2, 64B span (tid&3)*16 floats
    const int kvr = tid >> 2;
    const int kvc = (tid & 3) * 16;
    auto issueKV = [&](int kt, int buf) {
        if (kt <= ktmax) {
            const float* Kb = KVb + (size_t)(kt * 64 + kvr) * D3 + kvc;
            const uint32_t kd = kBase0 + (uint32_t)buf * (KVF * 4)
                              + (uint32_t)kvr * (AP * 4) + kvc * 4;
            const uint32_t vd = vBase0 + (uint32_t)buf * (KVF * 4)
                              + (uint32_t)kvr * (AP * 4) + kvc * 4;
            #pragma unroll
            for (int c = 0; c < 4; c++) {
                cp16(kd + c * 16, Kb + c * 4);
                cp16(vd + c * 16, Kb + 1024 + c * 4);
            }
        }
        asm volatile("cp.async.commit_group;" ::: "memory");
    };

    issueKV(0, 0);   // group 0 (also contains Q chunks)

    float s[8][4], o[8][4];
    float m0 = -1e30f, m1 = -1e30f, l0 = 0.0f, l1 = 0.0f;
    #pragma unroll
    for (int j = 0; j < 8; j++)
        #pragma unroll
        for (int e = 0; e < 4; e++) o[j][e] = 0.0f;

    const int pr = w * 16 + g;
    const uint32_t aRowOff = (uint32_t)(lane & 15) * (AP * 4) + (lane >> 4) * 16;
    const uint32_t bRowOff = (uint32_t)(lane & 7) * (AP * 4) + ((lane >> 3) & 1) * 16;
    const uint32_t qWarp = qBase + (uint32_t)(w * 16) * (AP * 4) + aRowOff;

    for (int kt = 0; kt <= ktmax; kt++) {
        issueKV(kt + 1, (kt + 1) & 1);
        asm volatile("cp.async.wait_group 1;" ::: "memory");
        __syncthreads();   // tile kt visible CTA-wide

        const int buf = kt & 1;
        const uint32_t kB = kBase0 + (uint32_t)buf * (KVF * 4);
        const float* Vs = sm + QF + 2 * KVF + buf * KVF;

        // ---- S = Q @ K^T (ldmatrix fragments) ----
        #pragma unroll
        for (int j = 0; j < 8; j++)
            #pragma unroll
            for (int e = 0; e < 4; e++) s[j][e] = 0.0f;

        #pragma unroll
        for (int kc = 0; kc < 8; kc++) {
            const uint4 a = ldsm_x4(qWarp + kc * 32);
            #pragma unroll
            for (int nt = 0; nt < 8; nt++) {
                const uint2 bb = ldsm_x2(kB + (uint32_t)(nt * 8) * (AP * 4)
                                            + kc * 32 + bRowOff);
                mma_tf32(s[nt], a, bb);
            }
        }

        // ---- fold 1/sqrt(64) (exact) ----
        #pragma unroll
        for (int nt = 0; nt < 8; nt++) {
            s[nt][0] *= 0.125f; s[nt][1] *= 0.125f;
            s[nt][2] *= 0.125f; s[nt][3] *= 0.125f;
        }

        // ---- causal mask on diagonal tiles ----
        if (kt >= 2 * qt) {
            const int r0  = qt * 128 + pr;
            const int kvb = kt * 64 + 2 * q;
            #pragma unroll
            for (int nt = 0; nt < 8; nt++) {
                const int c = kvb + nt * 8;
                if (c     > r0)     s[nt][0] = -1e30f;
                if (c + 1 > r0)     s[nt][1] = -1e30f;
                if (c     > r0 + 8) s[nt][2] = -1e30f;
                if (c + 1 > r0 + 8) s[nt][3] = -1e30f;
            }
        }

        // ---- online softmax (rows g / g+8) ----
        float mx0 = -1e30f, mx1 = -1e30f;
        #pragma unroll
        for (int nt = 0; nt < 8; nt++) {
            mx0 = fmaxf(mx0, fmaxf(s[nt][0], s[nt][1]));
            mx1 = fmaxf(mx1, fmaxf(s[nt][2], s[nt][3]));
        }
        mx0 = fmaxf(mx0, __shfl_xor_sync(0xffffffffu, mx0, 1, 4));
        mx0 = fmaxf(mx0, __shfl_xor_sync(0xffffffffu, mx0, 2, 4));
        mx1 = fmaxf(mx1, __shfl_xor_sync(0xffffffffu, mx1, 1, 4));
        mx1 = fmaxf(mx1, __shfl_xor_sync(0xffffffffu, mx1, 2, 4));

        const float mn0 = fmaxf(m0, mx0), mn1 = fmaxf(m1, mx1);
        const float al0 = __expf(m0 - mn0), al1 = __expf(m1 - mn1);
        m0 = mn0; m1 = mn1;

        float rs0 = 0.0f, rs1 = 0.0f;
        #pragma unroll
        for (int nt = 0; nt < 8; nt++) {
            s[nt][0] = __expf(s[nt][0] - mn0); rs0 += s[nt][0];
            s[nt][1] = __expf(s[nt][1] - mn0); rs0 += s[nt][1];
            s[nt][2] = __expf(s[nt][2] - mn1); rs1 += s[nt][2];
            s[nt][3] = __expf(s[nt][3] - mn1); rs1 += s[nt][3];
        }
        rs0 += __shfl_xor_sync(0xffffffffu, rs0, 1, 4);
        rs0 += __shfl_xor_sync(0xffffffffu, rs0, 2, 4);
        rs1 += __shfl_xor_sync(0xffffffffu, rs1, 1, 4);
        rs1 += __shfl_xor_sync(0xffffffffu, rs1, 2, 4);
        l0 = l0 * al0 + rs0;
        l1 = l1 * al1 + rs1;

        #pragma unroll
        for (int j = 0; j < 8; j++) {
            o[j][0] *= al0; o[j][1] *= al0;
            o[j][2] *= al1; o[j][3] *= al1;
        }

        // ---- O += P @ V (P C-frag as A-frag via sigma permutation) ----
        #pragma unroll
        for (int kc = 0; kc < 8; kc++) {
            uint4 a;
            a.x = f2tf32(s[kc][0]);
            a.y = f2tf32(s[kc][2]);
            a.z = f2tf32(s[kc][1]);
            a.w = f2tf32(s[kc][3]);
            const float* vr = &Vs[(kc * 8 + 2 * q) * AP];
            #pragma unroll
            for (int nd = 0; nd < 8; nd++) {
                uint2 bb;
                bb.x = __float_as_uint(vr[nd * 8 + g]);
                bb.y = __float_as_uint(vr[AP + nd * 8 + g]);
                mma_tf32(o[nd], a, bb);
            }
        }
        __syncthreads();   // all reads of buf kt&1 done before reuse at kt+2
    }

    // ---- epilogue: normalize, tf32-round (feeds proj GEMM), store ----
    float* ob = out + ((size_t)(b * S) + qt * 128) * 1024 + h * 64;
    const float inv0 = 1.0f / l0, inv1 = 1.0f / l1;
    #pragma unroll
    for (int nd = 0; nd < 8; nd++) {
        const int c = nd * 8 + 2 * q;
        float2 v0, v1;
        v0.x = tf32f(o[nd][0] * inv0); v0.y = tf32f(o[nd][1] * inv0);
        v1.x = tf32f(o[nd][2] * inv1); v1.y = tf32f(o[nd][3] * inv1);
        *(float2*)&ob[(size_t)pr * 1024 + c]       = v0;
        *(float2*)&ob[(size_t)(pr + 8) * 1024 + c] = v1;
    }
}

// ---------------- launch -------------------------------------------------
extern "C" void kernel_launch(void* const* d_in, const int* in_sizes, int n_in,
                              void* d_out, int out_size)
{
    const float* x      = (const float*)d_in[0];   // [4,2048,1024]
    const float* W_qkv  = (const float*)d_in[1];   // [1024,3072]
    const float* W_proj = (const float*)d_in[2];   // [1024,1024]
    const float* b_proj = (const float*)d_in[3];   // [1024]
    float* out = (float*)d_out;

    float *qkv = nullptr, *att = nullptr, *xr = nullptr, *wqT = nullptr, *wpT = nullptr;
    cudaGetSymbolAddress((void**)&qkv, g_qkv);
    cudaGetSymbolAddress((void**)&att, g_att);
    cudaGetSymbolAddress((void**)&xr,  g_xr);
    cudaGetSymbolAddress((void**)&wqT, g_wqT);
    cudaGetSymbolAddress((void**)&wpT, g_wpT);

    cudaFuncSetAttribute(attn_tc,
                         cudaFuncAttributeMaxDynamicSharedMemorySize, ATTN_SMEM);
    cudaFuncSetAttribute(gemm_cp,
                         cudaFuncAttributeMaxDynamicSharedMemorySize, GEMM_SMEM);

    const int M = 8192;

    // 0) pre-round x; transpose+round weights
    round_rna_vec<<<(M * 1024 / 4 + 255) / 256, 256>>>(
        (const float4*)x, (float4*)xr, M * 1024 / 4);
    transpose_rna<<<dim3(3072 / 32, 1024 / 32), 256>>>(W_qkv, wqT, 1024, 3072);
    transpose_rna<<<dim3(1024 / 32, 1024 / 32), 256>>>(W_proj, wpT, 1024, 1024);

    // 1) qkv = x @ W_qkv  (rounded output for raw attn staging)
    gemm_cp<<<dim3(3072 / 128, M / 128), 256, GEMM_SMEM>>>(
        xr, wqT, nullptr, qkv, M, 3072, 1024, 1);

    // 2) causal flash attention (tf32 mma.sync, cp.async pipelined)
    attn_tc<<<dim3(16, 16, 4), 256, ATTN_SMEM>>>(qkv, att);

    // 3) out = att @ W_proj + b_proj  (final output, unrounded)
    gemm_cp<<<dim3(1024 / 128, M / 128), 256, GEMM_SMEM>>>(
        att, wpT, b_proj, out, M, 1024, 1024, 0);
}